// round 6
// baseline (speedup 1.0000x reference)
#include <cuda_runtime.h>

// ---------------- problem constants ----------------
constexpr int Bn = 4;
constexpr int Sn = 4096;
constexpr int Hn = 16;
constexpr int BHn = 64;
constexpr int NSPLIT = 32;
constexpr int SCHUNK = Sn / NSPLIT;   // 128
constexpr int CH  = 64;               // s-rows per staged chunk
constexpr int NCH = SCHUNK / CH;      // 2
constexpr float PIC = 3.1415f;        // verbatim constant from reference

// ---------------- static device scratch ----------------
__device__ float    g_part  [NSPLIT * 64 * 8192];  // slot x bh x [64x(64|64)] fp32 partials
__device__ float    g_partKs[NSPLIT * 64 * 128];   // slot x bh x [ksum(64)|kpsum(64)]
__device__ unsigned g_Mst   [64 * 8192];           // bh x [128x64] tf32, PAIR layout
__device__ float    g_Ks    [64 * 128];            // bh x stacked [Ksum;Kpsum] fp32

// ---------------- helpers ----------------
__device__ __forceinline__ unsigned tf32c(float f) {
    unsigned r; asm("cvt.rna.tf32.f32 %0,%1;" : "=r"(r) : "f"(f)); return r;
}
__device__ __forceinline__ void mma8(float* c,
    unsigned a0, unsigned a1, unsigned a2, unsigned a3, unsigned b0, unsigned b1)
{
    asm volatile(
        "mma.sync.aligned.m16n8k8.row.col.f32.tf32.tf32.f32 "
        "{%0,%1,%2,%3},{%4,%5,%6,%7},{%8,%9},{%0,%1,%2,%3};"
        : "+f"(c[0]), "+f"(c[1]), "+f"(c[2]), "+f"(c[3])
        : "r"(a0), "r"(a1), "r"(a2), "r"(a3), "r"(b0), "r"(b1));
}
__device__ __forceinline__ float elu1(float v) { return v > 0.f ? v + 1.f : __expf(v); }
// A-operand fragment layout: logical (m,k) -> word index; MT = M/16
__device__ __forceinline__ int afrag(int m, int k, int MT) {
    return (((k >> 3) * MT + (m >> 4)) * 32 + (m & 7) * 4 + (k & 3)) * 4
           + ((m >> 3) & 1) + 2 * ((k >> 2) & 1);
}
// B-operand pair layout: (k,n) -> word index; reader LDS.64 gives (8ks+tig, n),(8ks+tig+4, n)
__device__ __forceinline__ int bpair(int k, int n, int NC) {
    return ((k >> 3) * NC + n) * 8 + (k & 3) * 2 + ((k >> 2) & 1);
}

// ===========================================================================
// Kernel 1 (tensor): per (bh, split):
//   kp = elu1(rawK @ Wk_h + bk)                 [mma tf32, 64x64x64 per chunk]
//   C[64x128] += kp^T @ [V | sinV]              [mma tf32, 64x128x64 per chunk]
//   ksum/kpsum via writer-side FMA + reduce.
// ===========================================================================
__global__ __launch_bounds__(256, 2)
void kv_kernel(const float4* __restrict__ key4, const float4* __restrict__ value4,
               const float4* __restrict__ wk_w4, const float* __restrict__ wk_b)
{
    extern __shared__ unsigned smu[];
    unsigned* sKf  = smu;                 // 4096  raw K, A-frag layout (M=64,K=64)
    unsigned* sWkP = sKf  + 4096;         // 4096  Wk, pair layout (K=64,N=64)
    unsigned* sV   = sWkP + 4096;         // 64 x 132  [V | sinV] row-major tf32
    unsigned* sAf  = sV   + 64 * 132;     // 4096  kp, A-frag layout for accum (M=x64,K=s64)
    float* sSin  = (float*)(sAf + 4096);  // 64
    float* sBias = sSin + 64;             // 64
    float* sKred = sBias + 64;            // 2 x 128

    const int bh = blockIdx.x, split = blockIdx.y;
    const int b  = bh >> 4,   h     = bh & 15;
    const int tid = threadIdx.x;
    const int lane = tid & 31, wid = tid >> 5;
    const int g = lane >> 2, tig = lane & 3;
    const int sbase = split * SCHUNK;

    // ---- stage Wk in pair layout (d-major thread mapping) + bias ----
    #pragma unroll
    for (int t = 0; t < 4; t++) {
        int idx = tid + t * 256; int d = idx & 63, c4 = idx >> 6;
        float4 w = wk_w4[d * 256 + h * 16 + c4];
        int kb = 4 * c4;
        sWkP[bpair(d, kb + 0, 64)] = tf32c(w.x);
        sWkP[bpair(d, kb + 1, 64)] = tf32c(w.y);
        sWkP[bpair(d, kb + 2, 64)] = tf32c(w.z);
        sWkP[bpair(d, kb + 3, 64)] = tf32c(w.w);
    }
    if (tid < 64) sBias[tid] = wk_b[h * 64 + tid];

    // ---- stage chunk 0 ----
    #pragma unroll
    for (int t = 0; t < 4; t++) {
        int idx = tid + t * 256; int r = idx >> 4, c4 = idx & 15;
        size_t gi = ((size_t)(b * Sn + sbase + r)) * 16 + c4;
        float4 k = key4[gi], v = value4[gi];
        int kb = 4 * c4;
        sKf[afrag(r, kb + 0, 4)] = tf32c(k.x);
        sKf[afrag(r, kb + 1, 4)] = tf32c(k.y);
        sKf[afrag(r, kb + 2, 4)] = tf32c(k.z);
        sKf[afrag(r, kb + 3, 4)] = tf32c(k.w);
        float sn = __sinf(PIC * (float)(sbase + r) / (float)Sn);
        *(uint4*)&sV[r * 132 + kb]      = make_uint4(tf32c(v.x), tf32c(v.y), tf32c(v.z), tf32c(v.w));
        *(uint4*)&sV[r * 132 + 64 + kb] = make_uint4(tf32c(v.x*sn), tf32c(v.y*sn), tf32c(v.z*sn), tf32c(v.w*sn));
    }
    if (tid < 64) sSin[tid] = __sinf(PIC * (float)(sbase + tid) / (float)Sn);
    __syncthreads();

    // proj tiling: warp covers rows 32*mt2..+31 (2 m-tiles), cols 16*nq..+15
    const int mt2 = wid & 1, nq = wid >> 1;
    // accum tiling: warp covers x-rows 32*xh..+31 (2 m-tiles), z-cols 32*zq..+31
    const int xh = wid & 1, zq = wid >> 1;

    float acc[2][4][4];
    #pragma unroll
    for (int i = 0; i < 2; i++)
        #pragma unroll
        for (int nt = 0; nt < 4; nt++)
            #pragma unroll
            for (int j = 0; j < 4; j++) acc[i][nt][j] = 0.f;
    float kc[2][2] = {{0.f,0.f},{0.f,0.f}}, kpc[2][2] = {{0.f,0.f},{0.f,0.f}};

    for (int cc = 0; cc < NCH; cc++) {
        // ---- projection mma ----
        float pc[2][2][4];
        #pragma unroll
        for (int i = 0; i < 2; i++)
            #pragma unroll
            for (int nt = 0; nt < 2; nt++) {
                int n = 16 * nq + 8 * nt + 2 * tig;
                pc[i][nt][0] = sBias[n]; pc[i][nt][1] = sBias[n + 1];
                pc[i][nt][2] = sBias[n]; pc[i][nt][3] = sBias[n + 1];
            }
        #pragma unroll
        for (int ks = 0; ks < 8; ks++) {
            uint4 a[2];
            #pragma unroll
            for (int i = 0; i < 2; i++)
                a[i] = *(const uint4*)&sKf[((ks * 4 + mt2 * 2 + i) * 32 + lane) * 4];
            #pragma unroll
            for (int nt = 0; nt < 2; nt++) {
                int n = 16 * nq + 8 * nt + g;
                uint2 bb = *(const uint2*)&sWkP[(ks * 64 + n) * 8 + tig * 2];
                #pragma unroll
                for (int i = 0; i < 2; i++)
                    mma8(pc[i][nt], a[i].x, a[i].y, a[i].z, a[i].w, bb.x, bb.y);
            }
        }
        // ---- elu + A-frag store (A of accum: (m=x, k=s)) + ksum FMA ----
        #pragma unroll
        for (int i = 0; i < 2; i++) {
            int s1 = 32 * mt2 + 16 * i + g, s2 = s1 + 8;
            float sn1 = sSin[s1], sn2 = sSin[s2];
            #pragma unroll
            for (int nt = 0; nt < 2; nt++) {
                int x0c = 16 * nq + 8 * nt + 2 * tig;
                float v00 = elu1(pc[i][nt][0]), v01 = elu1(pc[i][nt][1]);
                float v10 = elu1(pc[i][nt][2]), v11 = elu1(pc[i][nt][3]);
                kc [nt][0] += v00 + v10;          kc [nt][1] += v01 + v11;
                kpc[nt][0] += v00*sn1 + v10*sn2;  kpc[nt][1] += v01*sn1 + v11*sn2;
                sAf[afrag(x0c,     s1, 4)] = tf32c(v00);
                sAf[afrag(x0c + 1, s1, 4)] = tf32c(v01);
                sAf[afrag(x0c,     s2, 4)] = tf32c(v10);
                sAf[afrag(x0c + 1, s2, 4)] = tf32c(v11);
            }
        }
        __syncthreads();

        // ---- accumulation mma: C += kp^T @ [V|sinV] ----
        #pragma unroll
        for (int ks = 0; ks < 8; ks++) {
            uint4 a[2];
            #pragma unroll
            for (int i = 0; i < 2; i++)
                a[i] = *(const uint4*)&sAf[((ks * 4 + xh * 2 + i) * 32 + lane) * 4];
            #pragma unroll
            for (int nt = 0; nt < 4; nt++) {
                int z = 32 * zq + 8 * nt + g;
                unsigned b0 = sV[(8 * ks + tig)     * 132 + z];
                unsigned b1 = sV[(8 * ks + tig + 4) * 132 + z];
                #pragma unroll
                for (int i = 0; i < 2; i++)
                    mma8(acc[i][nt], a[i].x, a[i].y, a[i].z, a[i].w, b0, b1);
            }
        }
        __syncthreads();

        // ---- restage next chunk ----
        if (cc + 1 < NCH) {
            int scs = sbase + (cc + 1) * CH;
            #pragma unroll
            for (int t = 0; t < 4; t++) {
                int idx = tid + t * 256; int r = idx >> 4, c4 = idx & 15;
                size_t gi = ((size_t)(b * Sn + scs + r)) * 16 + c4;
                float4 k = key4[gi], v = value4[gi];
                int kb = 4 * c4;
                sKf[afrag(r, kb + 0, 4)] = tf32c(k.x);
                sKf[afrag(r, kb + 1, 4)] = tf32c(k.y);
                sKf[afrag(r, kb + 2, 4)] = tf32c(k.z);
                sKf[afrag(r, kb + 3, 4)] = tf32c(k.w);
                float sn = __sinf(PIC * (float)(scs + r) / (float)Sn);
                *(uint4*)&sV[r * 132 + kb]      = make_uint4(tf32c(v.x), tf32c(v.y), tf32c(v.z), tf32c(v.w));
                *(uint4*)&sV[r * 132 + 64 + kb] = make_uint4(tf32c(v.x*sn), tf32c(v.y*sn), tf32c(v.z*sn), tf32c(v.w*sn));
            }
            if (tid < 64) sSin[tid] = __sinf(PIC * (float)(scs + tid) / (float)Sn);
            __syncthreads();
        }
    }

    // ---- write fp32 C partials: [x][z 0..127] ----
    {
        size_t base = ((size_t)(split * 64 + bh)) * 8192;
        #pragma unroll
        for (int i = 0; i < 2; i++)
            #pragma unroll
            for (int nt = 0; nt < 4; nt++) {
                int x = 32 * xh + 16 * i + g;
                int z = 32 * zq + 8 * nt + 2 * tig;
                *(float2*)&g_part[base + (size_t)x       * 128 + z] = make_float2(acc[i][nt][0], acc[i][nt][1]);
                *(float2*)&g_part[base + (size_t)(x + 8) * 128 + z] = make_float2(acc[i][nt][2], acc[i][nt][3]);
            }
    }

    // ---- ksum reduce: sum over g-lanes (stride-4 shfl), stash, combine ----
    #pragma unroll
    for (int off = 4; off <= 16; off <<= 1)
        #pragma unroll
        for (int nt = 0; nt < 2; nt++)
            #pragma unroll
            for (int e = 0; e < 2; e++) {
                kc [nt][e] += __shfl_xor_sync(0xffffffffu, kc [nt][e], off);
                kpc[nt][e] += __shfl_xor_sync(0xffffffffu, kpc[nt][e], off);
            }
    if (g == 0) {
        #pragma unroll
        for (int nt = 0; nt < 2; nt++)
            #pragma unroll
            for (int e = 0; e < 2; e++) {
                int x = 16 * nq + 8 * nt + 2 * tig + e;
                sKred[mt2 * 128 + x]      = kc [nt][e];
                sKred[mt2 * 128 + 64 + x] = kpc[nt][e];
            }
    }
    __syncthreads();
    if (tid < 128)
        g_partKs[(split * 64 + bh) * 128 + tid] = sKred[tid] + sKred[128 + tid];
}

// ===========================================================================
// Kernel 2: per bh — reduce partials, fold V-proj + dense (fp32 SIMT):
//   G = Wv_h @ Wd_h ; bvd = bv_h @ Wd_h
//   [M;Mp] = Cstk @ G + [Ksum;Kpsum] (outer) bvd -> g_Mst (tf32, PAIR layout)
// ===========================================================================
constexpr int PAD = 68;
__global__ __launch_bounds__(256)
void mprep_kernel(const float* __restrict__ wv_w, const float* __restrict__ wv_b,
                  const float* __restrict__ dense_w)
{
    extern __shared__ float sm[];
    float* sC    = sm;                   // 128*68 (stacked rows [KV;KVp])
    float* sWv   = sC   + 128 * PAD;     // 64*68
    float* sWd   = sWv  + 64 * PAD;      // 64*68
    float* sG    = sWd  + 64 * PAD;      // 64*68
    float* sKsum = sG   + 64 * PAD;      // 128
    float* sBvd  = sKsum + 128;          // 64
    const float4* g_part4 = (const float4*)g_part;

    const int bh = blockIdx.x, h = bh & 15, tid = threadIdx.x;

    #pragma unroll
    for (int t = 0; t < 16; t++) {
        int i = tid + t * 256; int k = i >> 6, c = i & 63;
        sWv[k * PAD + c] = wv_w[k * 1024 + h * 64 + c];
        sWd[k * PAD + c] = dense_w[(h * 64 + k) * 64 + c];
    }
    // reduce partials; remap [x][z|z+64] -> stacked rows [x ; x+64]
    #pragma unroll
    for (int t = 0; t < 8; t++) {
        int idx = tid + t * 256;            // float4 index over 2048
        int x = idx >> 5, c8 = idx & 31;
        float4 s = make_float4(0.f, 0.f, 0.f, 0.f);
        for (int sl = 0; sl < NSPLIT; sl++) {
            float4 v = g_part4[((size_t)(sl * 64 + bh)) * 2048 + idx];
            s.x += v.x; s.y += v.y; s.z += v.z; s.w += v.w;
        }
        int row = (c8 < 16) ? x : (x + 64);
        int c4  = c8 & 15;
        *(float4*)&sC[row * PAD + c4 * 4] = s;
    }
    if (tid < 128) {
        float s = 0.f;
        for (int sl = 0; sl < NSPLIT; sl++) s += g_partKs[(sl * 64 + bh) * 128 + tid];
        sKsum[tid] = s;
        g_Ks[bh * 128 + tid] = s;
    }
    __syncthreads();

    const int r  = tid >> 2;
    const int c0 = (tid & 3) * 16;

    // G = Wv @ Wd
    {
        float a16[16];
        #pragma unroll
        for (int j = 0; j < 16; j++) a16[j] = 0.f;
        for (int kk = 0; kk < 64; kk++) {
            float a = sWv[r * PAD + kk];
            #pragma unroll
            for (int j = 0; j < 16; j++) a16[j] += a * sWd[kk * PAD + c0 + j];
        }
        #pragma unroll
        for (int j = 0; j < 16; j++) sG[r * PAD + c0 + j] = a16[j];
    }
    if (tid < 64) {
        float s = 0.f;
        for (int c = 0; c < 64; c++) s += wv_b[h * 64 + c] * sWd[c * PAD + tid];
        sBvd[tid] = s;
    }
    __syncthreads();

    // [M;Mp] = sC @ sG + ksum (outer) bvd -> g_Mst in PAIR layout
    {
        float m0[16], m1[16];
        #pragma unroll
        for (int j = 0; j < 16; j++) { m0[j] = 0.f; m1[j] = 0.f; }
        for (int kk = 0; kk < 64; kk++) {
            float a0 = sC[r * PAD + kk];
            float a1 = sC[(r + 64) * PAD + kk];
            #pragma unroll
            for (int j = 0; j < 16; j++) {
                float gv = sG[kk * PAD + c0 + j];
                m0[j] += a0 * gv; m1[j] += a1 * gv;
            }
        }
        float k0 = sKsum[r], k1 = sKsum[r + 64];
        #pragma unroll
        for (int j = 0; j < 16; j++) {
            m0[j] += k0 * sBvd[c0 + j];
            m1[j] += k1 * sBvd[c0 + j];
        }
        unsigned* dst = &g_Mst[(size_t)bh * 8192];
        #pragma unroll
        for (int j = 0; j < 16; j++) {
            dst[bpair(r,      c0 + j, 64)] = tf32c(m0[j]);
            dst[bpair(r + 64, c0 + j, 64)] = tf32c(m1[j]);
        }
    }
}

// ===========================================================================
// Kernel 3 (tensor): per (b, 64-row s-tile), loop heads:
//   q = elu1(rawQ @ Wq_h + bq)  [mma]; den; accO += den*([q|wq] @ [M;Mp]) [mma K=128]
// ===========================================================================
__global__ __launch_bounds__(256, 2)
void out_kernel(const float4* __restrict__ query4,
                const float4* __restrict__ wq_w4, const float* __restrict__ wq_b,
                const float* __restrict__ dense_b, float* __restrict__ out)
{
    extern __shared__ unsigned smu[];
    unsigned* sQrawF = smu;                  // 4096  raw Q, A-frag (M=64,K=64)
    unsigned* sWqP   = sQrawF + 4096;        // 4096  Wq head slice, pair layout
    unsigned* sB     = sWqP   + 4096;        // 8192  [M;Mp], pair layout (straight copy)
    unsigned* sQF    = sB     + 8192;        // 8192  [q|wq], A-frag (M=64,K=128)
    float* sKs  = (float*)(sQF + 8192);      // 128
    float* sWs  = sKs + 128;                 // 64
    float* sQb  = sWs + 64;                  // 64
    float* sDot = sQb + 64;                  // 64 x 4

    const int b  = blockIdx.y;
    const int s0 = blockIdx.x * 64;
    const int tid = threadIdx.x;
    const int lane = tid & 31, wid = tid >> 5;
    const int g = lane >> 2, tig = lane & 3;
    const int mt = wid & 3, nh = wid >> 2;
    const int m0 = mt * 16, n0 = nh * 32;

    // stage raw Q in A-frag layout (once per CTA)
    #pragma unroll
    for (int t = 0; t < 4; t++) {
        int idx = tid + t * 256; int r = idx >> 4, c4 = idx & 15;
        float4 q = query4[((size_t)(b * Sn + s0 + r)) * 16 + c4];
        int kb = 4 * c4;
        sQrawF[afrag(r, kb + 0, 4)] = tf32c(q.x);
        sQrawF[afrag(r, kb + 1, 4)] = tf32c(q.y);
        sQrawF[afrag(r, kb + 2, 4)] = tf32c(q.z);
        sQrawF[afrag(r, kb + 3, 4)] = tf32c(q.w);
    }
    if (tid < 64) {
        float ps = PIC * (float)(s0 + tid) / (float)Sn;
        sWs[tid] = __cosf(ps) + __sinf(ps);
    }

    float accO[4][4];
    #pragma unroll
    for (int nt = 0; nt < 4; nt++)
        #pragma unroll
        for (int j = 0; j < 4; j++) accO[nt][j] = 0.f;
    __syncthreads();

    const uint4* g_Mst4 = (const uint4*)g_Mst;

    for (int h = 0; h < Hn; h++) {
        const int bh = b * 16 + h;
        // ---- stage head data: Wq pair (d-major), B straight copy, Ks, bias ----
        #pragma unroll
        for (int t = 0; t < 4; t++) {
            int idx = tid + t * 256; int d = idx & 63, c4 = idx >> 6;
            float4 w = wq_w4[d * 256 + h * 16 + c4];
            int nb = 4 * c4;
            sWqP[bpair(d, nb + 0, 64)] = tf32c(w.x);
            sWqP[bpair(d, nb + 1, 64)] = tf32c(w.y);
            sWqP[bpair(d, nb + 2, 64)] = tf32c(w.z);
            sWqP[bpair(d, nb + 3, 64)] = tf32c(w.w);
        }
        #pragma unroll
        for (int t = 0; t < 8; t++) {
            int idx = tid + t * 256;
            *(uint4*)&sB[idx * 4] = g_Mst4[(size_t)bh * 2048 + idx];
        }
        if (tid < 128)      sKs[tid] = g_Ks[bh * 128 + tid];
        else if (tid < 192) sQb[tid - 128] = wq_b[h * 64 + (tid - 128)];
        __syncthreads();

        // ---- q projection mma (tile: rows m0..m0+15, cols n0..n0+31) ----
        float pc[4][4];
        #pragma unroll
        for (int nt = 0; nt < 4; nt++) {
            int col0 = n0 + 8 * nt + 2 * tig;
            pc[nt][0] = sQb[col0]; pc[nt][1] = sQb[col0 + 1];
            pc[nt][2] = sQb[col0]; pc[nt][3] = sQb[col0 + 1];
        }
        #pragma unroll
        for (int ks = 0; ks < 8; ks++) {
            uint4 a = *(const uint4*)&sQrawF[((ks * 4 + mt) * 32 + lane) * 4];
            #pragma unroll
            for (int nt = 0; nt < 4; nt++) {
                int n = n0 + 8 * nt + g;
                uint2 bb = *(const uint2*)&sWqP[(ks * 64 + n) * 8 + tig * 2];
                mma8(pc[nt], a.x, a.y, a.z, a.w, bb.x, bb.y);
            }
        }

        // ---- elu, partial denominators, store [q|wq] in A-frag layout ----
        {
            float w1 = sWs[m0 + g], w2 = sWs[m0 + g + 8];
            float d0a = 0.f, d1a = 0.f, d0b = 0.f, d1b = 0.f;
            #pragma unroll
            for (int nt = 0; nt < 4; nt++) {
                int x0c = n0 + 8 * nt + 2 * tig;
                float ks0 = sKs[x0c],      ks1 = sKs[x0c + 1];
                float kp0 = sKs[64 + x0c], kp1 = sKs[64 + x0c + 1];
                float v00 = elu1(pc[nt][0]), v01 = elu1(pc[nt][1]);
                float v10 = elu1(pc[nt][2]), v11 = elu1(pc[nt][3]);
                d0a += v00 * ks0 + v01 * ks1;  d1a += v00 * kp0 + v01 * kp1;
                d0b += v10 * ks0 + v11 * ks1;  d1b += v10 * kp0 + v11 * kp1;
                sQF[afrag(m0 + g,     x0c,      4)] = tf32c(v00);
                sQF[afrag(m0 + g,     x0c + 1,  4)] = tf32c(v01);
                sQF[afrag(m0 + g + 8, x0c,      4)] = tf32c(v10);
                sQF[afrag(m0 + g + 8, x0c + 1,  4)] = tf32c(v11);
                sQF[afrag(m0 + g,     64 + x0c,     4)] = tf32c(v00 * w1);
                sQF[afrag(m0 + g,     64 + x0c + 1, 4)] = tf32c(v01 * w1);
                sQF[afrag(m0 + g + 8, 64 + x0c,     4)] = tf32c(v10 * w2);
                sQF[afrag(m0 + g + 8, 64 + x0c + 1, 4)] = tf32c(v11 * w2);
            }
            d0a += __shfl_xor_sync(0xffffffffu, d0a, 1); d0a += __shfl_xor_sync(0xffffffffu, d0a, 2);
            d1a += __shfl_xor_sync(0xffffffffu, d1a, 1); d1a += __shfl_xor_sync(0xffffffffu, d1a, 2);
            d0b += __shfl_xor_sync(0xffffffffu, d0b, 1); d0b += __shfl_xor_sync(0xffffffffu, d0b, 2);
            d1b += __shfl_xor_sync(0xffffffffu, d1b, 1); d1b += __shfl_xor_sync(0xffffffffu, d1b, 2);
            if (tig == 0) {
                sDot[(m0 + g) * 4 + nh]         = d0a;
                sDot[(m0 + g) * 4 + 2 + nh]     = d1a;
                sDot[(m0 + g + 8) * 4 + nh]     = d0b;
                sDot[(m0 + g + 8) * 4 + 2 + nh] = d1b;
            }
        }
        __syncthreads();

        // ---- denominators ----
        int r1 = m0 + g, r2 = m0 + g + 8;
        float den1 = 1.0f / (sDot[r1 * 4] + sDot[r1 * 4 + 1]
                     + sWs[r1] * (sDot[r1 * 4 + 2] + sDot[r1 * 4 + 3]) + 1e-5f);
        float den2 = 1.0f / (sDot[r2 * 4] + sDot[r2 * 4 + 1]
                     + sWs[r2] * (sDot[r2 * 4 + 2] + sDot[r2 * 4 + 3]) + 1e-5f);

        // ---- o-GEMM mma: K=128 ----
        float oc[4][4];
        #pragma unroll
        for (int nt = 0; nt < 4; nt++)
            #pragma unroll
            for (int j = 0; j < 4; j++) oc[nt][j] = 0.f;
        #pragma unroll
        for (int kg = 0; kg < 16; kg++) {
            uint4 a = *(const uint4*)&sQF[((kg * 4 + mt) * 32 + lane) * 4];
            #pragma unroll
            for (int nt = 0; nt < 4; nt++) {
                int n = n0 + 8 * nt + g;
                uint2 bb = *(const uint2*)&sB[(kg * 64 + n) * 8 + tig * 2];
                mma8(oc[nt], a.x, a.y, a.z, a.w, bb.x, bb.y);
            }
        }
        #pragma unroll
        for (int nt = 0; nt < 4; nt++) {
            accO[nt][0] += den1 * oc[nt][0];
            accO[nt][1] += den1 * oc[nt][1];
            accO[nt][2] += den2 * oc[nt][2];
            accO[nt][3] += den2 * oc[nt][3];
        }
        __syncthreads();
    }

    // ---- epilogue: + dense_b ----
    #pragma unroll
    for (int nt = 0; nt < 4; nt++) {
        int col0 = n0 + 8 * nt + 2 * tig;
        float db0 = dense_b[col0], db1 = dense_b[col0 + 1];
        size_t o1 = ((size_t)(b * Sn + s0 + m0 + g)) * 64 + col0;
        size_t o2 = ((size_t)(b * Sn + s0 + m0 + g + 8)) * 64 + col0;
        out[o1]     = accO[nt][0] + db0;
        out[o1 + 1] = accO[nt][1] + db1;
        out[o2]     = accO[nt][2] + db0;
        out[o2 + 1] = accO[nt][3] + db1;
    }
}

// ---------------------------------------------------------------------------
extern "C" void kernel_launch(void* const* d_in, const int* in_sizes, int n_in,
                              void* d_out, int out_size)
{
    const float4* query4  = (const float4*)d_in[0];
    const float4* key4    = (const float4*)d_in[1];
    const float4* value4  = (const float4*)d_in[2];
    // d_in[3] = attn_mask (unused by the math)
    const float4* wq_w4   = (const float4*)d_in[4];
    const float*  wq_b    = (const float*)d_in[5];
    const float4* wk_w4   = (const float4*)d_in[6];
    const float*  wk_b    = (const float*)d_in[7];
    const float*  wv_w    = (const float*)d_in[8];
    const float*  wv_b    = (const float*)d_in[9];
    const float*  dense_w = (const float*)d_in[10];
    const float*  dense_b = (const float*)d_in[11];
    float* out = (float*)d_out;

    constexpr int SM_KV  = (4096 + 4096 + 64 * 132 + 4096 + 64 + 64 + 256) * 4;   // 84,480 B
    constexpr int SM_MP  = (128 * PAD + 3 * 64 * PAD + 128 + 64) * 4;             // 87,808 B
    constexpr int SM_OUT = (4096 + 4096 + 8192 + 8192 + 128 + 64 + 64 + 256) * 4; // 100,352 B

    cudaFuncSetAttribute(kv_kernel,    cudaFuncAttributeMaxDynamicSharedMemorySize, SM_KV);
    cudaFuncSetAttribute(mprep_kernel, cudaFuncAttributeMaxDynamicSharedMemorySize, SM_MP);
    cudaFuncSetAttribute(out_kernel,   cudaFuncAttributeMaxDynamicSharedMemorySize, SM_OUT);

    kv_kernel   <<<dim3(BHn, NSPLIT), 256, SM_KV >>>(key4, value4, wk_w4, wk_b);
    mprep_kernel<<<BHn,               256, SM_MP >>>(wv_w, wv_b, dense_w);
    out_kernel  <<<dim3(Sn / 64, Bn), 256, SM_OUT>>>(query4, wq_w4, wq_b, dense_b, out);
}

// round 7
// speedup vs baseline: 1.2462x; 1.2462x over previous
#include <cuda_runtime.h>

// ---------------- problem constants ----------------
constexpr int Bn = 4;
constexpr int Sn = 4096;
constexpr int Hn = 16;
constexpr int BHn = 64;
constexpr int NSPLIT = 32;
constexpr int SCHUNK = Sn / NSPLIT;   // 128
constexpr int CH  = 64;               // s-rows per staged chunk
constexpr int NCH = SCHUNK / CH;      // 2
constexpr float PIC = 3.1415f;        // verbatim constant from reference

// ---------------- static device scratch ----------------
__device__ float    g_part  [NSPLIT * 64 * 8192];  // slot x bh x [64x128] fp32 (KV | KVp)
__device__ float    g_partKs[NSPLIT * 64 * 128];   // slot x bh x [ksum|kpsum]
__device__ unsigned g_Mst   [64 * 8192];           // bh x [128x64] tf32 row-major
__device__ float    g_Ks    [64 * 128];            // bh x stacked [Ksum;Kpsum] fp32

// ---------------- helpers ----------------
__device__ __forceinline__ unsigned tf32c(float f) {
    unsigned r; asm("cvt.rna.tf32.f32 %0,%1;" : "=r"(r) : "f"(f)); return r;
}
__device__ __forceinline__ void mma8(float* c,
    unsigned a0, unsigned a1, unsigned a2, unsigned a3, unsigned b0, unsigned b1)
{
    asm volatile(
        "mma.sync.aligned.m16n8k8.row.col.f32.tf32.tf32.f32 "
        "{%0,%1,%2,%3},{%4,%5,%6,%7},{%8,%9},{%0,%1,%2,%3};"
        : "+f"(c[0]), "+f"(c[1]), "+f"(c[2]), "+f"(c[3])
        : "r"(a0), "r"(a1), "r"(a2), "r"(a3), "r"(b0), "r"(b1));
}
__device__ __forceinline__ float elu1(float v) { return v > 0.f ? v + 1.f : __expf(v); }

// ===========================================================================
// Kernel 1 (tensor): per (bh, split):
//   kp = elu1(rawK @ Wk_h + bk)        [mma, M64 N64 K64 per chunk]
//   C[64x128] += kp^T @ [V | sinV]     [mma, M64 N128 K64 per chunk]
//   ksum/kpsum harvested writer-side (FMA) + shfl/smem reduce.
// ===========================================================================
__global__ __launch_bounds__(256, 2)
void kv_kernel(const float4* __restrict__ key4, const float4* __restrict__ value4,
               const float4* __restrict__ wk_w4, const float* __restrict__ wk_b)
{
    extern __shared__ unsigned smu[];
    unsigned* sWk = smu;                  // 64 x 72   [d][n] tf32
    unsigned* sK  = sWk + 64 * 72;        // 64 x 68   [s][d] tf32
    unsigned* sV  = sK  + 64 * 68;        // 64 x 136  [s][z] tf32 (V | sinV)
    unsigned* sA  = sV  + 64 * 136;       // 64 x 76   [x][s] tf32 (kp^T), conflict-free
    float* sSin  = (float*)(sA + 64 * 76);  // 64
    float* sBias = sSin + 64;               // 64
    float* sKred = sBias + 64;              // 4 x 128

    const int bh = blockIdx.x, split = blockIdx.y;
    const int b  = bh >> 4,   h     = bh & 15;
    const int tid = threadIdx.x;
    const int lane = tid & 31, wid = tid >> 5;
    const int g = lane >> 2, tig = lane & 3;
    const int sbase = split * SCHUNK;

    // ---- stage Wk row-major [d][n] + bias ----
    #pragma unroll
    for (int t = 0; t < 4; t++) {
        int idx = tid + t * 256; int d = idx >> 4, c4 = idx & 15;
        float4 w = wk_w4[d * 256 + h * 16 + c4];
        *(uint4*)&sWk[d * 72 + c4 * 4] = make_uint4(tf32c(w.x), tf32c(w.y), tf32c(w.z), tf32c(w.w));
    }
    if (tid < 64) sBias[tid] = wk_b[h * 64 + tid];

    // ---- stage chunk 0 ----
    #pragma unroll
    for (int t = 0; t < 4; t++) {
        int idx = tid + t * 256; int r = idx >> 4, c4 = idx & 15;
        size_t gi = ((size_t)(b * Sn + sbase + r)) * 16 + c4;
        float4 k = key4[gi], v = value4[gi];
        int kb = 4 * c4;
        *(uint4*)&sK[r * 68 + kb] = make_uint4(tf32c(k.x), tf32c(k.y), tf32c(k.z), tf32c(k.w));
        float sn = __sinf(PIC * (float)(sbase + r) / (float)Sn);
        *(uint4*)&sV[r * 136 + kb]      = make_uint4(tf32c(v.x), tf32c(v.y), tf32c(v.z), tf32c(v.w));
        *(uint4*)&sV[r * 136 + 64 + kb] = make_uint4(tf32c(v.x*sn), tf32c(v.y*sn), tf32c(v.z*sn), tf32c(v.w*sn));
    }
    if (tid < 64) sSin[tid] = __sinf(PIC * (float)(sbase + tid) / (float)Sn);
    __syncthreads();

    // proj tiling:  m0p = 16*(wid&3), n0p = 32*(wid>>2)   (M64 x N64)
    const int m0p = (wid & 3) * 16;
    const int n0p = (wid >> 2) * 32;
    // accum tiling: x0 = 32*(wid&1), z0 = 32*(wid>>1)      (M64 x N128)
    const int x0 = (wid & 1) * 32;
    const int z0 = (wid >> 1) * 32;

    float acc[2][4][4];
    #pragma unroll
    for (int i = 0; i < 2; i++)
        #pragma unroll
        for (int nt = 0; nt < 4; nt++)
            #pragma unroll
            for (int j = 0; j < 4; j++) acc[i][nt][j] = 0.f;
    float kc[4][2], kpc[4][2];
    #pragma unroll
    for (int nt = 0; nt < 4; nt++) { kc[nt][0]=kc[nt][1]=kpc[nt][0]=kpc[nt][1]=0.f; }

    for (int cc = 0; cc < NCH; cc++) {
        // ---- projection mma: kp = rawK @ Wk + bias ----
        float pc[4][4];
        #pragma unroll
        for (int nt = 0; nt < 4; nt++) {
            int col0 = n0p + 8 * nt + 2 * tig;
            pc[nt][0] = sBias[col0]; pc[nt][1] = sBias[col0 + 1];
            pc[nt][2] = sBias[col0]; pc[nt][3] = sBias[col0 + 1];
        }
        #pragma unroll
        for (int ks = 0; ks < 8; ks++) {
            int k0 = ks * 8;
            unsigned a0 = sK[(m0p + g)     * 68 + k0 + tig];
            unsigned a1 = sK[(m0p + g + 8) * 68 + k0 + tig];
            unsigned a2 = sK[(m0p + g)     * 68 + k0 + tig + 4];
            unsigned a3 = sK[(m0p + g + 8) * 68 + k0 + tig + 4];
            #pragma unroll
            for (int nt = 0; nt < 4; nt++) {
                int n = n0p + 8 * nt + g;
                unsigned b0 = sWk[(k0 + tig)     * 72 + n];
                unsigned b1 = sWk[(k0 + tig + 4) * 72 + n];
                mma8(pc[nt], a0, a1, a2, a3, b0, b1);
            }
        }

        // ---- elu + store kp^T to sA[x][s] (stride 76, conflict-free) + ksum FMA ----
        {
            int s1 = m0p + g, s2 = m0p + g + 8;
            float sn1 = sSin[s1], sn2 = sSin[s2];
            #pragma unroll
            for (int nt = 0; nt < 4; nt++) {
                int col0 = n0p + 8 * nt + 2 * tig;
                float v00 = elu1(pc[nt][0]), v01 = elu1(pc[nt][1]);
                float v10 = elu1(pc[nt][2]), v11 = elu1(pc[nt][3]);
                kc [nt][0] += v00 + v10;           kc [nt][1] += v01 + v11;
                kpc[nt][0] += v00*sn1 + v10*sn2;   kpc[nt][1] += v01*sn1 + v11*sn2;
                sA[(col0)     * 76 + s1] = tf32c(v00);
                sA[(col0 + 1) * 76 + s1] = tf32c(v01);
                sA[(col0)     * 76 + s2] = tf32c(v10);
                sA[(col0 + 1) * 76 + s2] = tf32c(v11);
            }
        }
        __syncthreads();

        // ---- accumulation mma: C[x][z] += kp^T @ [V|sinV] ----
        #pragma unroll
        for (int ks = 0; ks < 8; ks++) {
            int k0 = ks * 8;
            unsigned a[2][4];
            #pragma unroll
            for (int i = 0; i < 2; i++) {
                int xr = x0 + 16 * i + g;
                a[i][0] = sA[xr       * 76 + k0 + tig];
                a[i][1] = sA[(xr + 8) * 76 + k0 + tig];
                a[i][2] = sA[xr       * 76 + k0 + tig + 4];
                a[i][3] = sA[(xr + 8) * 76 + k0 + tig + 4];
            }
            #pragma unroll
            for (int nt = 0; nt < 4; nt++) {
                int z = z0 + 8 * nt + g;
                unsigned b0 = sV[(k0 + tig)     * 136 + z];
                unsigned b1 = sV[(k0 + tig + 4) * 136 + z];
                #pragma unroll
                for (int i = 0; i < 2; i++)
                    mma8(acc[i][nt], a[i][0], a[i][1], a[i][2], a[i][3], b0, b1);
            }
        }
        __syncthreads();

        // ---- restage next chunk ----
        if (cc + 1 < NCH) {
            int scs = sbase + (cc + 1) * CH;
            #pragma unroll
            for (int t = 0; t < 4; t++) {
                int idx = tid + t * 256; int r = idx >> 4, c4 = idx & 15;
                size_t gi = ((size_t)(b * Sn + scs + r)) * 16 + c4;
                float4 k = key4[gi], v = value4[gi];
                int kb = 4 * c4;
                *(uint4*)&sK[r * 68 + kb] = make_uint4(tf32c(k.x), tf32c(k.y), tf32c(k.z), tf32c(k.w));
                float sn = __sinf(PIC * (float)(scs + r) / (float)Sn);
                *(uint4*)&sV[r * 136 + kb]      = make_uint4(tf32c(v.x), tf32c(v.y), tf32c(v.z), tf32c(v.w));
                *(uint4*)&sV[r * 136 + 64 + kb] = make_uint4(tf32c(v.x*sn), tf32c(v.y*sn), tf32c(v.z*sn), tf32c(v.w*sn));
            }
            if (tid < 64) sSin[tid] = __sinf(PIC * (float)(scs + tid) / (float)Sn);
            __syncthreads();
        }
    }

    // ---- write fp32 C partials: [x 0..63][z 0..127] ----
    {
        size_t base = ((size_t)(split * 64 + bh)) * 8192;
        #pragma unroll
        for (int i = 0; i < 2; i++)
            #pragma unroll
            for (int nt = 0; nt < 4; nt++) {
                int x = x0 + 16 * i + g;
                int z = z0 + 8 * nt + 2 * tig;
                *(float2*)&g_part[base + (size_t)x       * 128 + z] = make_float2(acc[i][nt][0], acc[i][nt][1]);
                *(float2*)&g_part[base + (size_t)(x + 8) * 128 + z] = make_float2(acc[i][nt][2], acc[i][nt][3]);
            }
    }

    // ---- ksum reduce: shfl over g-lanes, stash per m-tile, combine ----
    #pragma unroll
    for (int off = 4; off <= 16; off <<= 1)
        #pragma unroll
        for (int nt = 0; nt < 4; nt++)
            #pragma unroll
            for (int e = 0; e < 2; e++) {
                kc [nt][e] += __shfl_xor_sync(0xffffffffu, kc [nt][e], off);
                kpc[nt][e] += __shfl_xor_sync(0xffffffffu, kpc[nt][e], off);
            }
    if (g == 0) {
        int mt = wid & 3;
        #pragma unroll
        for (int nt = 0; nt < 4; nt++)
            #pragma unroll
            for (int e = 0; e < 2; e++) {
                int x = n0p + 8 * nt + 2 * tig + e;
                sKred[mt * 128 + x]      = kc [nt][e];
                sKred[mt * 128 + 64 + x] = kpc[nt][e];
            }
    }
    __syncthreads();
    if (tid < 128)
        g_partKs[(split * 64 + bh) * 128 + tid] =
            sKred[tid] + sKred[128 + tid] + sKred[256 + tid] + sKred[384 + tid];
}

// ===========================================================================
// Kernel 2: per bh — reduce partials, fold V-proj + dense (fp32 SIMT):
//   G = Wv_h @ Wd_h ; bvd = bv_h @ Wd_h
//   [M;Mp] = Cstk @ G + [Ksum;Kpsum] (outer) bvd -> g_Mst (tf32 row-major)
// ===========================================================================
constexpr int PAD = 68;
__global__ __launch_bounds__(256)
void mprep_kernel(const float* __restrict__ wv_w, const float* __restrict__ wv_b,
                  const float* __restrict__ dense_w)
{
    extern __shared__ float sm[];
    float* sC    = sm;                   // 128*68 (stacked rows [KV;KVp])
    float* sWv   = sC   + 128 * PAD;     // 64*68
    float* sWd   = sWv  + 64 * PAD;      // 64*68
    float* sG    = sWd  + 64 * PAD;      // 64*68
    float* sKsum = sG   + 64 * PAD;      // 128
    float* sBvd  = sKsum + 128;          // 64
    const float4* g_part4 = (const float4*)g_part;

    const int bh = blockIdx.x, h = bh & 15, tid = threadIdx.x;

    #pragma unroll
    for (int t = 0; t < 16; t++) {
        int i = tid + t * 256; int k = i >> 6, c = i & 63;
        sWv[k * PAD + c] = wv_w[k * 1024 + h * 64 + c];
        sWd[k * PAD + c] = dense_w[(h * 64 + k) * 64 + c];
    }
    // reduce partials; remap [x][z<64 | z>=64] -> stacked rows [x ; x+64]
    #pragma unroll
    for (int t = 0; t < 8; t++) {
        int idx = tid + t * 256;            // float4 index over 2048
        int x = idx >> 5, c8 = idx & 31;
        float4 s = make_float4(0.f, 0.f, 0.f, 0.f);
        for (int sl = 0; sl < NSPLIT; sl++) {
            float4 v = g_part4[((size_t)(sl * 64 + bh)) * 2048 + idx];
            s.x += v.x; s.y += v.y; s.z += v.z; s.w += v.w;
        }
        int row = (c8 < 16) ? x : (x + 64);
        int c4  = c8 & 15;
        *(float4*)&sC[row * PAD + c4 * 4] = s;
    }
    if (tid < 128) {
        float s = 0.f;
        for (int sl = 0; sl < NSPLIT; sl++) s += g_partKs[(sl * 64 + bh) * 128 + tid];
        sKsum[tid] = s;
        g_Ks[bh * 128 + tid] = s;
    }
    __syncthreads();

    const int r  = tid >> 2;
    const int c0 = (tid & 3) * 16;

    // G = Wv @ Wd
    {
        float a16[16];
        #pragma unroll
        for (int j = 0; j < 16; j++) a16[j] = 0.f;
        for (int kk = 0; kk < 64; kk++) {
            float a = sWv[r * PAD + kk];
            #pragma unroll
            for (int j = 0; j < 16; j++) a16[j] += a * sWd[kk * PAD + c0 + j];
        }
        #pragma unroll
        for (int j = 0; j < 16; j++) sG[r * PAD + c0 + j] = a16[j];
    }
    if (tid < 64) {
        float s = 0.f;
        for (int c = 0; c < 64; c++) s += wv_b[h * 64 + c] * sWd[c * PAD + tid];
        sBvd[tid] = s;
    }
    __syncthreads();

    // [M;Mp] = sC @ sG + ksum (outer) bvd -> g_Mst row-major
    {
        float m0[16], m1[16];
        #pragma unroll
        for (int j = 0; j < 16; j++) { m0[j] = 0.f; m1[j] = 0.f; }
        for (int kk = 0; kk < 64; kk++) {
            float a0 = sC[r * PAD + kk];
            float a1 = sC[(r + 64) * PAD + kk];
            #pragma unroll
            for (int j = 0; j < 16; j++) {
                float gv = sG[kk * PAD + c0 + j];
                m0[j] += a0 * gv; m1[j] += a1 * gv;
            }
        }
        float k0 = sKsum[r], k1 = sKsum[r + 64];
        #pragma unroll
        for (int j = 0; j < 16; j++) {
            m0[j] += k0 * sBvd[c0 + j];
            m1[j] += k1 * sBvd[c0 + j];
        }
        int ob0 = bh * 8192 + r * 64 + c0;
        int ob1 = bh * 8192 + (r + 64) * 64 + c0;
        #pragma unroll
        for (int j = 0; j < 16; j++) {
            g_Mst[ob0 + j] = tf32c(m0[j]);
            g_Mst[ob1 + j] = tf32c(m1[j]);
        }
    }
}

// ===========================================================================
// Kernel 3 (tensor): per (b, 64-row s-tile), loop heads  (R5-proven):
//   q = elu1(rawQ @ Wq_h + bq)  [mma]; den; accO += den*([q|wq] @ [M;Mp]) [mma K=128]
// ===========================================================================
__global__ __launch_bounds__(256, 2)
void out_kernel(const float4* __restrict__ query4,
                const float4* __restrict__ wq_w4, const float* __restrict__ wq_b,
                const float* __restrict__ dense_b, float* __restrict__ out)
{
    extern __shared__ unsigned smu[];
    unsigned* sQraw = smu;                  // 64 x 68  tf32 raw Q
    unsigned* sWq   = sQraw + 64 * 68;      // 64 x 72  tf32 Wq head slice
    unsigned* sB    = sWq   + 64 * 72;      // 128 x 72 tf32 [M;Mp]
    unsigned* sQ    = sB    + 128 * 72;     // 64 x 132 tf32 [q | w*q]
    float* sKs  = (float*)(sQ + 64 * 132);  // 128
    float* sWs  = sKs + 128;                // 64
    float* sQb  = sWs + 64;                 // 64
    float* sDot = sQb + 64;                 // 64 x 4

    const int b  = blockIdx.y;
    const int s0 = blockIdx.x * 64;
    const int tid = threadIdx.x;
    const int lane = tid & 31, wid = tid >> 5;
    const int g = lane >> 2, tig = lane & 3;
    const int mt = wid & 3, nh = wid >> 2;
    const int m0 = mt * 16, n0 = nh * 32;

    #pragma unroll
    for (int t = 0; t < 4; t++) {
        int idx = tid + t * 256; int r = idx >> 4, c4 = idx & 15;
        float4 q = query4[((size_t)(b * Sn + s0 + r)) * 16 + c4];
        *(uint4*)&sQraw[r * 68 + c4 * 4] = make_uint4(tf32c(q.x), tf32c(q.y), tf32c(q.z), tf32c(q.w));
    }
    if (tid < 64) {
        float ps = PIC * (float)(s0 + tid) / (float)Sn;
        sWs[tid] = __cosf(ps) + __sinf(ps);
    }

    float accO[4][4];
    #pragma unroll
    for (int nt = 0; nt < 4; nt++)
        #pragma unroll
        for (int j = 0; j < 4; j++) accO[nt][j] = 0.f;
    __syncthreads();

    const uint4* g_Mst4 = (const uint4*)g_Mst;

    for (int h = 0; h < Hn; h++) {
        const int bh = b * 16 + h;
        #pragma unroll
        for (int t = 0; t < 4; t++) {
            int idx = tid + t * 256; int d = idx >> 4, c4 = idx & 15;
            float4 w = wq_w4[d * 256 + h * 16 + c4];
            *(uint4*)&sWq[d * 72 + c4 * 4] = make_uint4(tf32c(w.x), tf32c(w.y), tf32c(w.z), tf32c(w.w));
        }
        #pragma unroll
        for (int t = 0; t < 8; t++) {
            int idx = tid + t * 256; int r = idx >> 4, c4 = idx & 15;
            *(uint4*)&sB[r * 72 + c4 * 4] = g_Mst4[(size_t)bh * 2048 + idx];
        }
        if (tid < 128)      sKs[tid] = g_Ks[bh * 128 + tid];
        else if (tid < 192) sQb[tid - 128] = wq_b[h * 64 + (tid - 128)];
        __syncthreads();

        // ---- q projection mma ----
        float pc[4][4];
        #pragma unroll
        for (int nt = 0; nt < 4; nt++) {
            int col0 = n0 + 8 * nt + 2 * tig;
            pc[nt][0] = sQb[col0]; pc[nt][1] = sQb[col0 + 1];
            pc[nt][2] = sQb[col0]; pc[nt][3] = sQb[col0 + 1];
        }
        #pragma unroll
        for (int ks = 0; ks < 8; ks++) {
            int k0 = ks * 8;
            unsigned a0 = sQraw[(m0 + g)     * 68 + k0 + tig];
            unsigned a1 = sQraw[(m0 + g + 8) * 68 + k0 + tig];
            unsigned a2 = sQraw[(m0 + g)     * 68 + k0 + tig + 4];
            unsigned a3 = sQraw[(m0 + g + 8) * 68 + k0 + tig + 4];
            #pragma unroll
            for (int nt = 0; nt < 4; nt++) {
                int n = n0 + 8 * nt + g;
                unsigned b0 = sWq[(k0 + tig)     * 72 + n];
                unsigned b1 = sWq[(k0 + tig + 4) * 72 + n];
                mma8(pc[nt], a0, a1, a2, a3, b0, b1);
            }
        }

        // ---- elu, partial denominators, store [q|wq] ----
        {
            float w1 = sWs[m0 + g], w2 = sWs[m0 + g + 8];
            int r1 = (m0 + g) * 132, r2 = (m0 + g + 8) * 132;
            float d0a = 0.f, d1a = 0.f, d0b = 0.f, d1b = 0.f;
            #pragma unroll
            for (int nt = 0; nt < 4; nt++) {
                int col0 = n0 + 8 * nt + 2 * tig;
                float ks0 = sKs[col0],      ks1 = sKs[col0 + 1];
                float kp0 = sKs[64 + col0], kp1 = sKs[64 + col0 + 1];
                float v00 = elu1(pc[nt][0]), v01 = elu1(pc[nt][1]);
                float v10 = elu1(pc[nt][2]), v11 = elu1(pc[nt][3]);
                d0a += v00 * ks0 + v01 * ks1;  d1a += v00 * kp0 + v01 * kp1;
                d0b += v10 * ks0 + v11 * ks1;  d1b += v10 * kp0 + v11 * kp1;
                sQ[r1 + col0]          = tf32c(v00);
                sQ[r1 + col0 + 1]      = tf32c(v01);
                sQ[r2 + col0]          = tf32c(v10);
                sQ[r2 + col0 + 1]      = tf32c(v11);
                sQ[r1 + 64 + col0]     = tf32c(v00 * w1);
                sQ[r1 + 64 + col0 + 1] = tf32c(v01 * w1);
                sQ[r2 + 64 + col0]     = tf32c(v10 * w2);
                sQ[r2 + 64 + col0 + 1] = tf32c(v11 * w2);
            }
            d0a += __shfl_xor_sync(0xffffffffu, d0a, 1); d0a += __shfl_xor_sync(0xffffffffu, d0a, 2);
            d1a += __shfl_xor_sync(0xffffffffu, d1a, 1); d1a += __shfl_xor_sync(0xffffffffu, d1a, 2);
            d0b += __shfl_xor_sync(0xffffffffu, d0b, 1); d0b += __shfl_xor_sync(0xffffffffu, d0b, 2);
            d1b += __shfl_xor_sync(0xffffffffu, d1b, 1); d1b += __shfl_xor_sync(0xffffffffu, d1b, 2);
            if (tig == 0) {
                sDot[(m0 + g) * 4 + nh]         = d0a;
                sDot[(m0 + g) * 4 + 2 + nh]     = d1a;
                sDot[(m0 + g + 8) * 4 + nh]     = d0b;
                sDot[(m0 + g + 8) * 4 + 2 + nh] = d1b;
            }
        }
        __syncthreads();

        int r1 = m0 + g, r2 = m0 + g + 8;
        float den1 = 1.0f / (sDot[r1 * 4] + sDot[r1 * 4 + 1]
                     + sWs[r1] * (sDot[r1 * 4 + 2] + sDot[r1 * 4 + 3]) + 1e-5f);
        float den2 = 1.0f / (sDot[r2 * 4] + sDot[r2 * 4 + 1]
                     + sWs[r2] * (sDot[r2 * 4 + 2] + sDot[r2 * 4 + 3]) + 1e-5f);

        // ---- o-GEMM mma: K=128 ----
        float oc[4][4];
        #pragma unroll
        for (int nt = 0; nt < 4; nt++)
            #pragma unroll
            for (int j = 0; j < 4; j++) oc[nt][j] = 0.f;
        #pragma unroll
        for (int ks = 0; ks < 16; ks++) {
            int k0 = ks * 8;
            unsigned a0 = sQ[(m0 + g)     * 132 + k0 + tig];
            unsigned a1 = sQ[(m0 + g + 8) * 132 + k0 + tig];
            unsigned a2 = sQ[(m0 + g)     * 132 + k0 + tig + 4];
            unsigned a3 = sQ[(m0 + g + 8) * 132 + k0 + tig + 4];
            #pragma unroll
            for (int nt = 0; nt < 4; nt++) {
                int n = n0 + 8 * nt + g;
                unsigned b0 = sB[(k0 + tig)     * 72 + n];
                unsigned b1 = sB[(k0 + tig + 4) * 72 + n];
                mma8(oc[nt], a0, a1, a2, a3, b0, b1);
            }
        }
        #pragma unroll
        for (int nt = 0; nt < 4; nt++) {
            accO[nt][0] += den1 * oc[nt][0];
            accO[nt][1] += den1 * oc[nt][1];
            accO[nt][2] += den2 * oc[nt][2];
            accO[nt][3] += den2 * oc[nt][3];
        }
        __syncthreads();
    }

    // ---- epilogue: + dense_b ----
    #pragma unroll
    for (int nt = 0; nt < 4; nt++) {
        int col0 = n0 + 8 * nt + 2 * tig;
        float db0 = dense_b[col0], db1 = dense_b[col0 + 1];
        size_t o1 = ((size_t)(b * Sn + s0 + m0 + g)) * 64 + col0;
        size_t o2 = ((size_t)(b * Sn + s0 + m0 + g + 8)) * 64 + col0;
        out[o1]     = accO[nt][0] + db0;
        out[o1 + 1] = accO[nt][1] + db1;
        out[o2]     = accO[nt][2] + db0;
        out[o2 + 1] = accO[nt][3] + db1;
    }
}

// ---------------------------------------------------------------------------
extern "C" void kernel_launch(void* const* d_in, const int* in_sizes, int n_in,
                              void* d_out, int out_size)
{
    const float4* query4  = (const float4*)d_in[0];
    const float4* key4    = (const float4*)d_in[1];
    const float4* value4  = (const float4*)d_in[2];
    // d_in[3] = attn_mask (unused by the math)
    const float4* wq_w4   = (const float4*)d_in[4];
    const float*  wq_b    = (const float*)d_in[5];
    const float4* wk_w4   = (const float4*)d_in[6];
    const float*  wk_b    = (const float*)d_in[7];
    const float*  wv_w    = (const float*)d_in[8];
    const float*  wv_b    = (const float*)d_in[9];
    const float*  dense_w = (const float*)d_in[10];
    const float*  dense_b = (const float*)d_in[11];
    float* out = (float*)d_out;

    constexpr int SM_KV  = (64*72 + 64*68 + 64*136 + 64*76 + 64 + 64 + 512) * 4;      // 95,232 B
    constexpr int SM_MP  = (128 * PAD + 3 * 64 * PAD + 128 + 64) * 4;                 // 87,808 B
    constexpr int SM_OUT = (64*68 + 64*72 + 128*72 + 64*132 + 128+64+64+256) * 4;     // 108,544 B

    cudaFuncSetAttribute(kv_kernel,    cudaFuncAttributeMaxDynamicSharedMemorySize, SM_KV);
    cudaFuncSetAttribute(mprep_kernel, cudaFuncAttributeMaxDynamicSharedMemorySize, SM_MP);
    cudaFuncSetAttribute(out_kernel,   cudaFuncAttributeMaxDynamicSharedMemorySize, SM_OUT);

    kv_kernel   <<<dim3(BHn, NSPLIT), 256, SM_KV >>>(key4, value4, wk_w4, wk_b);
    mprep_kernel<<<BHn,               256, SM_MP >>>(wv_w, wv_b, dense_w);
    out_kernel  <<<dim3(Sn / 64, Bn), 256, SM_OUT>>>(query4, wq_w4, wq_b, dense_b, out);
}

// round 8
// speedup vs baseline: 1.3985x; 1.1223x over previous
#include <cuda_runtime.h>

// ---------------- problem constants ----------------
constexpr int Bn = 4;
constexpr int Sn = 4096;
constexpr int Hn = 16;
constexpr int BHn = 64;
constexpr int NSPLIT = 16;
constexpr int SCHUNK = Sn / NSPLIT;   // 256
constexpr int CH  = 64;               // s-rows per staged chunk
constexpr int NCH = SCHUNK / CH;      // 4
constexpr float PIC = 3.1415f;        // verbatim constant from reference

// ---------------- static device scratch ----------------
__device__ float    g_part  [NSPLIT * 64 * 8192];  // slot x bh x [64x128] fp32 (KV | KVp)
__device__ float    g_partKs[NSPLIT * 64 * 128];   // slot x bh x [ksum|kpsum]
__device__ unsigned g_Mst   [64 * 8192];           // bh x [128x64] tf32, PAIR layout
__device__ float    g_Ks    [64 * 128];            // bh x stacked [Ksum;Kpsum] fp32

// ---------------- helpers ----------------
__device__ __forceinline__ unsigned tf32c(float f) {
    unsigned r; asm("cvt.rna.tf32.f32 %0,%1;" : "=r"(r) : "f"(f)); return r;
}
__device__ __forceinline__ void mma8(float* c,
    unsigned a0, unsigned a1, unsigned a2, unsigned a3, unsigned b0, unsigned b1)
{
    asm volatile(
        "mma.sync.aligned.m16n8k8.row.col.f32.tf32.tf32.f32 "
        "{%0,%1,%2,%3},{%4,%5,%6,%7},{%8,%9},{%0,%1,%2,%3};"
        : "+f"(c[0]), "+f"(c[1]), "+f"(c[2]), "+f"(c[3])
        : "r"(a0), "r"(a1), "r"(a2), "r"(a3), "r"(b0), "r"(b1));
}
__device__ __forceinline__ float elu1(float v) { return v > 0.f ? v + 1.f : __expf(v); }
// B-operand pair layout: (k,n) -> word index. Reader LDS.64 at ((k>>3)*NC+n)*8+2*tig
// yields words (k=8ks+tig, n) and (k=8ks+tig+4, n). Conflict-free (banks 8(g&3)+2tig).
__device__ __forceinline__ int bpair(int k, int n, int NC) {
    return ((k >> 3) * NC + n) * 8 + (k & 3) * 2 + ((k >> 2) & 1);
}

// ===========================================================================
// Kernel 1 (tensor): per (bh, split):
//   kp = elu1(rawK @ Wk_h + bk)        [mma, M64 N64 K64 per chunk]
//   C[64x128] += kp^T @ [V | sinV]     [mma, M64 N128 K64 per chunk]
//   ksum/kpsum harvested writer-side (FMA) + shfl/smem reduce.
// ===========================================================================
__global__ __launch_bounds__(256, 2)
void kv_kernel(const float4* __restrict__ key4, const float4* __restrict__ value4,
               const float4* __restrict__ wk_w4, const float* __restrict__ wk_b)
{
    extern __shared__ unsigned smu[];
    unsigned* sWk = smu;                  // 64 x 72   [d][n] tf32
    unsigned* sK  = sWk + 64 * 72;        // 64 x 68   [s][d] tf32
    unsigned* sV  = sK  + 64 * 68;        // 64 x 136  [s][z] tf32 (V | sinV)
    unsigned* sA  = sV  + 64 * 136;       // 64 x 76   [x][s] tf32 (kp^T), conflict-free
    float* sSin  = (float*)(sA + 64 * 76);  // 64
    float* sBias = sSin + 64;               // 64
    float* sKred = sBias + 64;              // 4 x 128

    const int bh = blockIdx.x, split = blockIdx.y;
    const int b  = bh >> 4,   h     = bh & 15;
    const int tid = threadIdx.x;
    const int lane = tid & 31, wid = tid >> 5;
    const int g = lane >> 2, tig = lane & 3;
    const int sbase = split * SCHUNK;

    // ---- stage Wk row-major [d][n] + bias ----
    #pragma unroll
    for (int t = 0; t < 4; t++) {
        int idx = tid + t * 256; int d = idx >> 4, c4 = idx & 15;
        float4 w = wk_w4[d * 256 + h * 16 + c4];
        *(uint4*)&sWk[d * 72 + c4 * 4] = make_uint4(tf32c(w.x), tf32c(w.y), tf32c(w.z), tf32c(w.w));
    }
    if (tid < 64) sBias[tid] = wk_b[h * 64 + tid];

    // ---- stage chunk 0 ----
    #pragma unroll
    for (int t = 0; t < 4; t++) {
        int idx = tid + t * 256; int r = idx >> 4, c4 = idx & 15;
        size_t gi = ((size_t)(b * Sn + sbase + r)) * 16 + c4;
        float4 k = key4[gi], v = value4[gi];
        int kb = 4 * c4;
        *(uint4*)&sK[r * 68 + kb] = make_uint4(tf32c(k.x), tf32c(k.y), tf32c(k.z), tf32c(k.w));
        float sn = __sinf(PIC * (float)(sbase + r) / (float)Sn);
        *(uint4*)&sV[r * 136 + kb]      = make_uint4(tf32c(v.x), tf32c(v.y), tf32c(v.z), tf32c(v.w));
        *(uint4*)&sV[r * 136 + 64 + kb] = make_uint4(tf32c(v.x*sn), tf32c(v.y*sn), tf32c(v.z*sn), tf32c(v.w*sn));
    }
    if (tid < 64) sSin[tid] = __sinf(PIC * (float)(sbase + tid) / (float)Sn);
    __syncthreads();

    // proj tiling:  m0p = 16*(wid&3), n0p = 32*(wid>>2)   (M64 x N64)
    const int m0p = (wid & 3) * 16;
    const int n0p = (wid >> 2) * 32;
    // accum tiling: x0 = 32*(wid&1), z0 = 32*(wid>>1)      (M64 x N128)
    const int x0 = (wid & 1) * 32;
    const int z0 = (wid >> 1) * 32;

    float acc[2][4][4];
    #pragma unroll
    for (int i = 0; i < 2; i++)
        #pragma unroll
        for (int nt = 0; nt < 4; nt++)
            #pragma unroll
            for (int j = 0; j < 4; j++) acc[i][nt][j] = 0.f;
    float kc[4][2], kpc[4][2];
    #pragma unroll
    for (int nt = 0; nt < 4; nt++) { kc[nt][0]=kc[nt][1]=kpc[nt][0]=kpc[nt][1]=0.f; }

    for (int cc = 0; cc < NCH; cc++) {
        // ---- projection mma: kp = rawK @ Wk + bias ----
        float pc[4][4];
        #pragma unroll
        for (int nt = 0; nt < 4; nt++) {
            int col0 = n0p + 8 * nt + 2 * tig;
            pc[nt][0] = sBias[col0]; pc[nt][1] = sBias[col0 + 1];
            pc[nt][2] = sBias[col0]; pc[nt][3] = sBias[col0 + 1];
        }
        #pragma unroll
        for (int ks = 0; ks < 8; ks++) {
            int k0 = ks * 8;
            unsigned a0 = sK[(m0p + g)     * 68 + k0 + tig];
            unsigned a1 = sK[(m0p + g + 8) * 68 + k0 + tig];
            unsigned a2 = sK[(m0p + g)     * 68 + k0 + tig + 4];
            unsigned a3 = sK[(m0p + g + 8) * 68 + k0 + tig + 4];
            #pragma unroll
            for (int nt = 0; nt < 4; nt++) {
                int n = n0p + 8 * nt + g;
                unsigned b0 = sWk[(k0 + tig)     * 72 + n];
                unsigned b1 = sWk[(k0 + tig + 4) * 72 + n];
                mma8(pc[nt], a0, a1, a2, a3, b0, b1);
            }
        }

        // ---- elu + store kp^T to sA[x][s] (stride 76, conflict-free) + ksum FMA ----
        {
            int s1 = m0p + g, s2 = m0p + g + 8;
            float sn1 = sSin[s1], sn2 = sSin[s2];
            #pragma unroll
            for (int nt = 0; nt < 4; nt++) {
                int col0 = n0p + 8 * nt + 2 * tig;
                float v00 = elu1(pc[nt][0]), v01 = elu1(pc[nt][1]);
                float v10 = elu1(pc[nt][2]), v11 = elu1(pc[nt][3]);
                kc [nt][0] += v00 + v10;           kc [nt][1] += v01 + v11;
                kpc[nt][0] += v00*sn1 + v10*sn2;   kpc[nt][1] += v01*sn1 + v11*sn2;
                sA[(col0)     * 76 + s1] = tf32c(v00);
                sA[(col0 + 1) * 76 + s1] = tf32c(v01);
                sA[(col0)     * 76 + s2] = tf32c(v10);
                sA[(col0 + 1) * 76 + s2] = tf32c(v11);
            }
        }
        __syncthreads();

        // ---- accumulation mma: C[x][z] += kp^T @ [V|sinV] ----
        #pragma unroll
        for (int ks = 0; ks < 8; ks++) {
            int k0 = ks * 8;
            unsigned a[2][4];
            #pragma unroll
            for (int i = 0; i < 2; i++) {
                int xr = x0 + 16 * i + g;
                a[i][0] = sA[xr       * 76 + k0 + tig];
                a[i][1] = sA[(xr + 8) * 76 + k0 + tig];
                a[i][2] = sA[xr       * 76 + k0 + tig + 4];
                a[i][3] = sA[(xr + 8) * 76 + k0 + tig + 4];
            }
            #pragma unroll
            for (int nt = 0; nt < 4; nt++) {
                int z = z0 + 8 * nt + g;
                unsigned b0 = sV[(k0 + tig)     * 136 + z];
                unsigned b1 = sV[(k0 + tig + 4) * 136 + z];
                #pragma unroll
                for (int i = 0; i < 2; i++)
                    mma8(acc[i][nt], a[i][0], a[i][1], a[i][2], a[i][3], b0, b1);
            }
        }
        __syncthreads();

        // ---- restage next chunk ----
        if (cc + 1 < NCH) {
            int scs = sbase + (cc + 1) * CH;
            #pragma unroll
            for (int t = 0; t < 4; t++) {
                int idx = tid + t * 256; int r = idx >> 4, c4 = idx & 15;
                size_t gi = ((size_t)(b * Sn + scs + r)) * 16 + c4;
                float4 k = key4[gi], v = value4[gi];
                int kb = 4 * c4;
                *(uint4*)&sK[r * 68 + kb] = make_uint4(tf32c(k.x), tf32c(k.y), tf32c(k.z), tf32c(k.w));
                float sn = __sinf(PIC * (float)(scs + r) / (float)Sn);
                *(uint4*)&sV[r * 136 + kb]      = make_uint4(tf32c(v.x), tf32c(v.y), tf32c(v.z), tf32c(v.w));
                *(uint4*)&sV[r * 136 + 64 + kb] = make_uint4(tf32c(v.x*sn), tf32c(v.y*sn), tf32c(v.z*sn), tf32c(v.w*sn));
            }
            if (tid < 64) sSin[tid] = __sinf(PIC * (float)(scs + tid) / (float)Sn);
            __syncthreads();
        }
    }

    // ---- write fp32 C partials: [x 0..63][z 0..127] ----
    {
        size_t base = ((size_t)(split * 64 + bh)) * 8192;
        #pragma unroll
        for (int i = 0; i < 2; i++)
            #pragma unroll
            for (int nt = 0; nt < 4; nt++) {
                int x = x0 + 16 * i + g;
                int z = z0 + 8 * nt + 2 * tig;
                *(float2*)&g_part[base + (size_t)x       * 128 + z] = make_float2(acc[i][nt][0], acc[i][nt][1]);
                *(float2*)&g_part[base + (size_t)(x + 8) * 128 + z] = make_float2(acc[i][nt][2], acc[i][nt][3]);
            }
    }

    // ---- ksum reduce: shfl over g-lanes, stash per m-tile, combine ----
    #pragma unroll
    for (int off = 4; off <= 16; off <<= 1)
        #pragma unroll
        for (int nt = 0; nt < 4; nt++)
            #pragma unroll
            for (int e = 0; e < 2; e++) {
                kc [nt][e] += __shfl_xor_sync(0xffffffffu, kc [nt][e], off);
                kpc[nt][e] += __shfl_xor_sync(0xffffffffu, kpc[nt][e], off);
            }
    if (g == 0) {
        int mt = wid & 3;
        #pragma unroll
        for (int nt = 0; nt < 4; nt++)
            #pragma unroll
            for (int e = 0; e < 2; e++) {
                int x = n0p + 8 * nt + 2 * tig + e;
                sKred[mt * 128 + x]      = kc [nt][e];
                sKred[mt * 128 + 64 + x] = kpc[nt][e];
            }
    }
    __syncthreads();
    if (tid < 128)
        g_partKs[(split * 64 + bh) * 128 + tid] =
            sKred[tid] + sKred[128 + tid] + sKred[256 + tid] + sKred[384 + tid];
}

// ===========================================================================
// Kernel 2: per bh — reduce partials, fold V-proj + dense (fp32 SIMT):
//   G = Wv_h @ Wd_h ; bvd = bv_h @ Wd_h
//   [M;Mp] = Cstk @ G + [Ksum;Kpsum] (outer) bvd -> g_Mst (tf32, PAIR layout)
// ===========================================================================
constexpr int PAD = 68;
__global__ __launch_bounds__(256)
void mprep_kernel(const float* __restrict__ wv_w, const float* __restrict__ wv_b,
                  const float* __restrict__ dense_w)
{
    extern __shared__ float sm[];
    float* sC    = sm;                   // 128*68 (stacked rows [KV;KVp])
    float* sWv   = sC   + 128 * PAD;     // 64*68
    float* sWd   = sWv  + 64 * PAD;      // 64*68
    float* sG    = sWd  + 64 * PAD;      // 64*68
    float* sKsum = sG   + 64 * PAD;      // 128
    float* sBvd  = sKsum + 128;          // 64
    const float4* g_part4 = (const float4*)g_part;

    const int bh = blockIdx.x, h = bh & 15, tid = threadIdx.x;

    #pragma unroll
    for (int t = 0; t < 16; t++) {
        int i = tid + t * 256; int k = i >> 6, c = i & 63;
        sWv[k * PAD + c] = wv_w[k * 1024 + h * 64 + c];
        sWd[k * PAD + c] = dense_w[(h * 64 + k) * 64 + c];
    }
    // reduce partials; remap [x][z<64 | z>=64] -> stacked rows [x ; x+64]
    #pragma unroll
    for (int t = 0; t < 8; t++) {
        int idx = tid + t * 256;            // float4 index over 2048
        int x = idx >> 5, c8 = idx & 31;
        float4 s = make_float4(0.f, 0.f, 0.f, 0.f);
        for (int sl = 0; sl < NSPLIT; sl++) {
            float4 v = g_part4[((size_t)(sl * 64 + bh)) * 2048 + idx];
            s.x += v.x; s.y += v.y; s.z += v.z; s.w += v.w;
        }
        int row = (c8 < 16) ? x : (x + 64);
        int c4  = c8 & 15;
        *(float4*)&sC[row * PAD + c4 * 4] = s;
    }
    if (tid < 128) {
        float s = 0.f;
        for (int sl = 0; sl < NSPLIT; sl++) s += g_partKs[(sl * 64 + bh) * 128 + tid];
        sKsum[tid] = s;
        g_Ks[bh * 128 + tid] = s;
    }
    __syncthreads();

    const int r  = tid >> 2;
    const int c0 = (tid & 3) * 16;

    // G = Wv @ Wd
    {
        float a16[16];
        #pragma unroll
        for (int j = 0; j < 16; j++) a16[j] = 0.f;
        for (int kk = 0; kk < 64; kk++) {
            float a = sWv[r * PAD + kk];
            #pragma unroll
            for (int j = 0; j < 16; j++) a16[j] += a * sWd[kk * PAD + c0 + j];
        }
        #pragma unroll
        for (int j = 0; j < 16; j++) sG[r * PAD + c0 + j] = a16[j];
    }
    if (tid < 64) {
        float s = 0.f;
        for (int c = 0; c < 64; c++) s += wv_b[h * 64 + c] * sWd[c * PAD + tid];
        sBvd[tid] = s;
    }
    __syncthreads();

    // [M;Mp] = sC @ sG + ksum (outer) bvd -> g_Mst in PAIR layout (free permute)
    {
        float m0[16], m1[16];
        #pragma unroll
        for (int j = 0; j < 16; j++) { m0[j] = 0.f; m1[j] = 0.f; }
        for (int kk = 0; kk < 64; kk++) {
            float a0 = sC[r * PAD + kk];
            float a1 = sC[(r + 64) * PAD + kk];
            #pragma unroll
            for (int j = 0; j < 16; j++) {
                float gv = sG[kk * PAD + c0 + j];
                m0[j] += a0 * gv; m1[j] += a1 * gv;
            }
        }
        float k0 = sKsum[r], k1 = sKsum[r + 64];
        #pragma unroll
        for (int j = 0; j < 16; j++) {
            m0[j] += k0 * sBvd[c0 + j];
            m1[j] += k1 * sBvd[c0 + j];
        }
        unsigned* dst = &g_Mst[(size_t)bh * 8192];
        #pragma unroll
        for (int j = 0; j < 16; j++) {
            dst[bpair(r,      c0 + j, 64)] = tf32c(m0[j]);
            dst[bpair(r + 64, c0 + j, 64)] = tf32c(m1[j]);
        }
    }
}

// ===========================================================================
// Kernel 3 (tensor): per (b, 64-row s-tile), loop heads:
//   q = elu1(rawQ @ Wq_h + bq)  [mma]; den; accO += den*([q|wq] @ [M;Mp]) [mma K=128]
//   o-GEMM B in pair layout: staged with straight uint4 copies, read via LDS.64.
// ===========================================================================
__global__ __launch_bounds__(256, 2)
void out_kernel(const float4* __restrict__ query4,
                const float4* __restrict__ wq_w4, const float* __restrict__ wq_b,
                const float* __restrict__ dense_b, float* __restrict__ out)
{
    extern __shared__ unsigned smu[];
    unsigned* sQraw = smu;                  // 64 x 68  tf32 raw Q
    unsigned* sWq   = sQraw + 64 * 68;      // 64 x 72  tf32 Wq head slice
    unsigned* sB    = sWq   + 64 * 72;      // 8192     [M;Mp] pair layout
    unsigned* sQ    = sB    + 8192;         // 64 x 132 tf32 [q | w*q]
    float* sKs  = (float*)(sQ + 64 * 132);  // 128
    float* sWs  = sKs + 128;                // 64
    float* sQb  = sWs + 64;                 // 64
    float* sDot = sQb + 64;                 // 64 x 4

    const int b  = blockIdx.y;
    const int s0 = blockIdx.x * 64;
    const int tid = threadIdx.x;
    const int lane = tid & 31, wid = tid >> 5;
    const int g = lane >> 2, tig = lane & 3;
    const int mt = wid & 3, nh = wid >> 2;
    const int m0 = mt * 16, n0 = nh * 32;

    #pragma unroll
    for (int t = 0; t < 4; t++) {
        int idx = tid + t * 256; int r = idx >> 4, c4 = idx & 15;
        float4 q = query4[((size_t)(b * Sn + s0 + r)) * 16 + c4];
        *(uint4*)&sQraw[r * 68 + c4 * 4] = make_uint4(tf32c(q.x), tf32c(q.y), tf32c(q.z), tf32c(q.w));
    }
    if (tid < 64) {
        float ps = PIC * (float)(s0 + tid) / (float)Sn;
        sWs[tid] = __cosf(ps) + __sinf(ps);
    }

    float accO[4][4];
    #pragma unroll
    for (int nt = 0; nt < 4; nt++)
        #pragma unroll
        for (int j = 0; j < 4; j++) accO[nt][j] = 0.f;
    __syncthreads();

    const uint4* g_Mst4 = (const uint4*)g_Mst;

    for (int h = 0; h < Hn; h++) {
        const int bh = b * 16 + h;
        #pragma unroll
        for (int t = 0; t < 4; t++) {
            int idx = tid + t * 256; int d = idx >> 4, c4 = idx & 15;
            float4 w = wq_w4[d * 256 + h * 16 + c4];
            *(uint4*)&sWq[d * 72 + c4 * 4] = make_uint4(tf32c(w.x), tf32c(w.y), tf32c(w.z), tf32c(w.w));
        }
        #pragma unroll
        for (int t = 0; t < 8; t++) {
            int idx = tid + t * 256;
            *(uint4*)&sB[idx * 4] = g_Mst4[(size_t)bh * 2048 + idx];
        }
        if (tid < 128)      sKs[tid] = g_Ks[bh * 128 + tid];
        else if (tid < 192) sQb[tid - 128] = wq_b[h * 64 + (tid - 128)];
        __syncthreads();

        // ---- q projection mma ----
        float pc[4][4];
        #pragma unroll
        for (int nt = 0; nt < 4; nt++) {
            int col0 = n0 + 8 * nt + 2 * tig;
            pc[nt][0] = sQb[col0]; pc[nt][1] = sQb[col0 + 1];
            pc[nt][2] = sQb[col0]; pc[nt][3] = sQb[col0 + 1];
        }
        #pragma unroll
        for (int ks = 0; ks < 8; ks++) {
            int k0 = ks * 8;
            unsigned a0 = sQraw[(m0 + g)     * 68 + k0 + tig];
            unsigned a1 = sQraw[(m0 + g + 8) * 68 + k0 + tig];
            unsigned a2 = sQraw[(m0 + g)     * 68 + k0 + tig + 4];
            unsigned a3 = sQraw[(m0 + g + 8) * 68 + k0 + tig + 4];
            #pragma unroll
            for (int nt = 0; nt < 4; nt++) {
                int n = n0 + 8 * nt + g;
                unsigned b0 = sWq[(k0 + tig)     * 72 + n];
                unsigned b1 = sWq[(k0 + tig + 4) * 72 + n];
                mma8(pc[nt], a0, a1, a2, a3, b0, b1);
            }
        }

        // ---- elu, partial denominators, store [q|wq] ----
        {
            float w1 = sWs[m0 + g], w2 = sWs[m0 + g + 8];
            int r1 = (m0 + g) * 132, r2 = (m0 + g + 8) * 132;
            float d0a = 0.f, d1a = 0.f, d0b = 0.f, d1b = 0.f;
            #pragma unroll
            for (int nt = 0; nt < 4; nt++) {
                int col0 = n0 + 8 * nt + 2 * tig;
                float ks0 = sKs[col0],      ks1 = sKs[col0 + 1];
                float kp0 = sKs[64 + col0], kp1 = sKs[64 + col0 + 1];
                float v00 = elu1(pc[nt][0]), v01 = elu1(pc[nt][1]);
                float v10 = elu1(pc[nt][2]), v11 = elu1(pc[nt][3]);
                d0a += v00 * ks0 + v01 * ks1;  d1a += v00 * kp0 + v01 * kp1;
                d0b += v10 * ks0 + v11 * ks1;  d1b += v10 * kp0 + v11 * kp1;
                sQ[r1 + col0]          = tf32c(v00);
                sQ[r1 + col0 + 1]      = tf32c(v01);
                sQ[r2 + col0]          = tf32c(v10);
                sQ[r2 + col0 + 1]      = tf32c(v11);
                sQ[r1 + 64 + col0]     = tf32c(v00 * w1);
                sQ[r1 + 64 + col0 + 1] = tf32c(v01 * w1);
                sQ[r2 + 64 + col0]     = tf32c(v10 * w2);
                sQ[r2 + 64 + col0 + 1] = tf32c(v11 * w2);
            }
            d0a += __shfl_xor_sync(0xffffffffu, d0a, 1); d0a += __shfl_xor_sync(0xffffffffu, d0a, 2);
            d1a += __shfl_xor_sync(0xffffffffu, d1a, 1); d1a += __shfl_xor_sync(0xffffffffu, d1a, 2);
            d0b += __shfl_xor_sync(0xffffffffu, d0b, 1); d0b += __shfl_xor_sync(0xffffffffu, d0b, 2);
            d1b += __shfl_xor_sync(0xffffffffu, d1b, 1); d1b += __shfl_xor_sync(0xffffffffu, d1b, 2);
            if (tig == 0) {
                sDot[(m0 + g) * 4 + nh]         = d0a;
                sDot[(m0 + g) * 4 + 2 + nh]     = d1a;
                sDot[(m0 + g + 8) * 4 + nh]     = d0b;
                sDot[(m0 + g + 8) * 4 + 2 + nh] = d1b;
            }
        }
        __syncthreads();

        int r1 = m0 + g, r2 = m0 + g + 8;
        float den1 = 1.0f / (sDot[r1 * 4] + sDot[r1 * 4 + 1]
                     + sWs[r1] * (sDot[r1 * 4 + 2] + sDot[r1 * 4 + 3]) + 1e-5f);
        float den2 = 1.0f / (sDot[r2 * 4] + sDot[r2 * 4 + 1]
                     + sWs[r2] * (sDot[r2 * 4 + 2] + sDot[r2 * 4 + 3]) + 1e-5f);

        // ---- o-GEMM mma: K=128, B via pair-layout LDS.64 ----
        float oc[4][4];
        #pragma unroll
        for (int nt = 0; nt < 4; nt++)
            #pragma unroll
            for (int j = 0; j < 4; j++) oc[nt][j] = 0.f;
        #pragma unroll
        for (int ks = 0; ks < 16; ks++) {
            int k0 = ks * 8;
            unsigned a0 = sQ[(m0 + g)     * 132 + k0 + tig];
            unsigned a1 = sQ[(m0 + g + 8) * 132 + k0 + tig];
            unsigned a2 = sQ[(m0 + g)     * 132 + k0 + tig + 4];
            unsigned a3 = sQ[(m0 + g + 8) * 132 + k0 + tig + 4];
            #pragma unroll
            for (int nt = 0; nt < 4; nt++) {
                int n = n0 + 8 * nt + g;
                uint2 bb = *(const uint2*)&sB[(ks * 64 + n) * 8 + tig * 2];
                mma8(oc[nt], a0, a1, a2, a3, bb.x, bb.y);
            }
        }
        #pragma unroll
        for (int nt = 0; nt < 4; nt++) {
            accO[nt][0] += den1 * oc[nt][0];
            accO[nt][1] += den1 * oc[nt][1];
            accO[nt][2] += den2 * oc[nt][2];
            accO[nt][3] += den2 * oc[nt][3];
        }
        __syncthreads();
    }

    // ---- epilogue: + dense_b ----
    #pragma unroll
    for (int nt = 0; nt < 4; nt++) {
        int col0 = n0 + 8 * nt + 2 * tig;
        float db0 = dense_b[col0], db1 = dense_b[col0 + 1];
        size_t o1 = ((size_t)(b * Sn + s0 + m0 + g)) * 64 + col0;
        size_t o2 = ((size_t)(b * Sn + s0 + m0 + g + 8)) * 64 + col0;
        out[o1]     = accO[nt][0] + db0;
        out[o1 + 1] = accO[nt][1] + db1;
        out[o2]     = accO[nt][2] + db0;
        out[o2 + 1] = accO[nt][3] + db1;
    }
}

// ---------------------------------------------------------------------------
extern "C" void kernel_launch(void* const* d_in, const int* in_sizes, int n_in,
                              void* d_out, int out_size)
{
    const float4* query4  = (const float4*)d_in[0];
    const float4* key4    = (const float4*)d_in[1];
    const float4* value4  = (const float4*)d_in[2];
    // d_in[3] = attn_mask (unused by the math)
    const float4* wq_w4   = (const float4*)d_in[4];
    const float*  wq_b    = (const float*)d_in[5];
    const float4* wk_w4   = (const float4*)d_in[6];
    const float*  wk_b    = (const float*)d_in[7];
    const float*  wv_w    = (const float*)d_in[8];
    const float*  wv_b    = (const float*)d_in[9];
    const float*  dense_w = (const float*)d_in[10];
    const float*  dense_b = (const float*)d_in[11];
    float* out = (float*)d_out;

    constexpr int SM_KV  = (64*72 + 64*68 + 64*136 + 64*76 + 64 + 64 + 512) * 4;      // 95,232 B
    constexpr int SM_MP  = (128 * PAD + 3 * 64 * PAD + 128 + 64) * 4;                 // 87,808 B
    constexpr int SM_OUT = (64*68 + 64*72 + 8192 + 64*132 + 128+64+64+256) * 4;       // 108,544 B

    cudaFuncSetAttribute(kv_kernel,    cudaFuncAttributeMaxDynamicSharedMemorySize, SM_KV);
    cudaFuncSetAttribute(mprep_kernel, cudaFuncAttributeMaxDynamicSharedMemorySize, SM_MP);
    cudaFuncSetAttribute(out_kernel,   cudaFuncAttributeMaxDynamicSharedMemorySize, SM_OUT);

    kv_kernel   <<<dim3(BHn, NSPLIT), 256, SM_KV >>>(key4, value4, wk_w4, wk_b);
    mprep_kernel<<<BHn,               256, SM_MP >>>(wv_w, wv_b, dense_w);
    out_kernel  <<<dim3(Sn / 64, Bn), 256, SM_OUT>>>(query4, wq_w4, wq_b, dense_b, out);
}

// round 9
// speedup vs baseline: 1.4319x; 1.0238x over previous
#include <cuda_runtime.h>

// ---------------- problem constants ----------------
constexpr int Bn = 4;
constexpr int Sn = 4096;
constexpr int Hn = 16;
constexpr int BHn = 64;
constexpr int NSPLIT = 16;
constexpr int SCHUNK = Sn / NSPLIT;   // 256
constexpr int CH  = 64;               // s-rows per staged chunk
constexpr int NCH = SCHUNK / CH;      // 4
constexpr float PIC = 3.1415f;        // verbatim constant from reference

// ---------------- static device scratch ----------------
__device__ float    g_part  [NSPLIT * 64 * 8192];  // slot x bh x [64x128] fp32 (KV | KVp)
__device__ float    g_partKs[NSPLIT * 64 * 128];   // slot x bh x [ksum|kpsum]
__device__ unsigned g_Mst   [64 * 8192];           // bh x M/Mp-interleaved pair layout
__device__ float    g_Ks    [64 * 128];            // bh x stacked [Ksum;Kpsum] fp32

// ---------------- helpers ----------------
__device__ __forceinline__ unsigned tf32c(float f) {
    unsigned r; asm("cvt.rna.tf32.f32 %0,%1;" : "=r"(r) : "f"(f)); return r;
}
__device__ __forceinline__ void mma8(float* c,
    unsigned a0, unsigned a1, unsigned a2, unsigned a3, unsigned b0, unsigned b1)
{
    asm volatile(
        "mma.sync.aligned.m16n8k8.row.col.f32.tf32.tf32.f32 "
        "{%0,%1,%2,%3},{%4,%5,%6,%7},{%8,%9},{%0,%1,%2,%3};"
        : "+f"(c[0]), "+f"(c[1]), "+f"(c[2]), "+f"(c[3])
        : "r"(a0), "r"(a1), "r"(a2), "r"(a3), "r"(b0), "r"(b1));
}
__device__ __forceinline__ float elu1(float v) { return v > 0.f ? v + 1.f : __expf(v); }
// B pair layout (single matrix): reader LDS.64 at ((ks*NC+n)*8 + 2*tig) yields
// fragments (k=8ks+tig, n) and (k=8ks+tig+4, n). Conflict-free reads.
__device__ __forceinline__ int bpair(int k, int n, int NC) {
    return ((k >> 3) * NC + n) * 8 + (k & 3) * 2 + ((k >> 2) & 1);
}
// M/Mp interleaved pair layout: word(kk,n)+0 = M(kk,n), +1 = Mp(kk,n).
// Reader LDS.128 at ((ks*64+n)*16 + 4*tig) yields {M(8ks+tig), Mp(8ks+tig),
// M(8ks+tig+4), Mp(8ks+tig+4)}. Conflict-free.
__device__ __forceinline__ int bpair2(int kk, int n) {
    return ((kk >> 3) * 64 + n) * 16 + (kk & 3) * 4 + ((kk >> 2) & 1) * 2;
}

// ===========================================================================
// Kernel 1 (tensor): per (bh, split):
//   kp = elu1(rawK @ Wk_h + bk)        [mma, M64 N64 K64 per chunk; Wk pair layout]
//   C[64x128] += kp^T @ [V | sinV]     [mma, M64 N128 K64 per chunk]
//   ksum/kpsum harvested writer-side (FMA) + shfl/smem reduce.
// ===========================================================================
__global__ __launch_bounds__(256, 2)
void kv_kernel(const float4* __restrict__ key4, const float4* __restrict__ value4,
               const float4* __restrict__ wk_w4, const float* __restrict__ wk_b)
{
    extern __shared__ unsigned smu[];
    unsigned* sWk = smu;                  // 4096      Wk pair layout (K=64,N=64)
    unsigned* sK  = sWk + 4096;           // 64 x 68   [s][d] tf32
    unsigned* sV  = sK  + 64 * 68;        // 64 x 136  [s][z] tf32 (V | sinV)
    unsigned* sA  = sV  + 64 * 136;       // 64 x 76   [x][s] tf32 (kp^T), conflict-free
    float* sSin  = (float*)(sA + 64 * 76);  // 64
    float* sBias = sSin + 64;               // 64
    float* sKred = sBias + 64;              // 4 x 128

    const int bh = blockIdx.x, split = blockIdx.y;
    const int b  = bh >> 4,   h     = bh & 15;
    const int tid = threadIdx.x;
    const int lane = tid & 31, wid = tid >> 5;
    const int g = lane >> 2, tig = lane & 3;
    const int sbase = split * SCHUNK;

    // ---- stage Wk in pair layout (one-time; scatter conflicts acceptable) ----
    #pragma unroll
    for (int t = 0; t < 4; t++) {
        int idx = tid + t * 256; int d = idx & 63, c4 = idx >> 6;
        float4 w = wk_w4[d * 256 + h * 16 + c4];
        int nb = 4 * c4;
        sWk[bpair(d, nb + 0, 64)] = tf32c(w.x);
        sWk[bpair(d, nb + 1, 64)] = tf32c(w.y);
        sWk[bpair(d, nb + 2, 64)] = tf32c(w.z);
        sWk[bpair(d, nb + 3, 64)] = tf32c(w.w);
    }
    if (tid < 64) sBias[tid] = wk_b[h * 64 + tid];

    // ---- stage chunk 0 ----
    #pragma unroll
    for (int t = 0; t < 4; t++) {
        int idx = tid + t * 256; int r = idx >> 4, c4 = idx & 15;
        size_t gi = ((size_t)(b * Sn + sbase + r)) * 16 + c4;
        float4 k = key4[gi], v = value4[gi];
        int kb = 4 * c4;
        *(uint4*)&sK[r * 68 + kb] = make_uint4(tf32c(k.x), tf32c(k.y), tf32c(k.z), tf32c(k.w));
        float sn = __sinf(PIC * (float)(sbase + r) / (float)Sn);
        *(uint4*)&sV[r * 136 + kb]      = make_uint4(tf32c(v.x), tf32c(v.y), tf32c(v.z), tf32c(v.w));
        *(uint4*)&sV[r * 136 + 64 + kb] = make_uint4(tf32c(v.x*sn), tf32c(v.y*sn), tf32c(v.z*sn), tf32c(v.w*sn));
    }
    if (tid < 64) sSin[tid] = __sinf(PIC * (float)(sbase + tid) / (float)Sn);
    __syncthreads();

    // proj tiling:  m0p = 16*(wid&3), n0p = 32*(wid>>2)   (M64 x N64)
    const int m0p = (wid & 3) * 16;
    const int n0p = (wid >> 2) * 32;
    // accum tiling: x0 = 32*(wid&1), z0 = 32*(wid>>1)      (M64 x N128)
    const int x0 = (wid & 1) * 32;
    const int z0 = (wid >> 1) * 32;

    float acc[2][4][4];
    #pragma unroll
    for (int i = 0; i < 2; i++)
        #pragma unroll
        for (int nt = 0; nt < 4; nt++)
            #pragma unroll
            for (int j = 0; j < 4; j++) acc[i][nt][j] = 0.f;
    float kc[4][2], kpc[4][2];
    #pragma unroll
    for (int nt = 0; nt < 4; nt++) { kc[nt][0]=kc[nt][1]=kpc[nt][0]=kpc[nt][1]=0.f; }

    for (int cc = 0; cc < NCH; cc++) {
        // ---- projection mma: kp = rawK @ Wk + bias (B via pair LDS.64) ----
        float pc[4][4];
        #pragma unroll
        for (int nt = 0; nt < 4; nt++) {
            int col0 = n0p + 8 * nt + 2 * tig;
            pc[nt][0] = sBias[col0]; pc[nt][1] = sBias[col0 + 1];
            pc[nt][2] = sBias[col0]; pc[nt][3] = sBias[col0 + 1];
        }
        #pragma unroll
        for (int ks = 0; ks < 8; ks++) {
            int k0 = ks * 8;
            unsigned a0 = sK[(m0p + g)     * 68 + k0 + tig];
            unsigned a1 = sK[(m0p + g + 8) * 68 + k0 + tig];
            unsigned a2 = sK[(m0p + g)     * 68 + k0 + tig + 4];
            unsigned a3 = sK[(m0p + g + 8) * 68 + k0 + tig + 4];
            #pragma unroll
            for (int nt = 0; nt < 4; nt++) {
                int n = n0p + 8 * nt + g;
                uint2 bb = *(const uint2*)&sWk[(ks * 64 + n) * 8 + tig * 2];
                mma8(pc[nt], a0, a1, a2, a3, bb.x, bb.y);
            }
        }

        // ---- elu + store kp^T to sA[x][s] (stride 76, conflict-free) + ksum FMA ----
        {
            int s1 = m0p + g, s2 = m0p + g + 8;
            float sn1 = sSin[s1], sn2 = sSin[s2];
            #pragma unroll
            for (int nt = 0; nt < 4; nt++) {
                int col0 = n0p + 8 * nt + 2 * tig;
                float v00 = elu1(pc[nt][0]), v01 = elu1(pc[nt][1]);
                float v10 = elu1(pc[nt][2]), v11 = elu1(pc[nt][3]);
                kc [nt][0] += v00 + v10;           kc [nt][1] += v01 + v11;
                kpc[nt][0] += v00*sn1 + v10*sn2;   kpc[nt][1] += v01*sn1 + v11*sn2;
                sA[(col0)     * 76 + s1] = tf32c(v00);
                sA[(col0 + 1) * 76 + s1] = tf32c(v01);
                sA[(col0)     * 76 + s2] = tf32c(v10);
                sA[(col0 + 1) * 76 + s2] = tf32c(v11);
            }
        }
        __syncthreads();

        // ---- accumulation mma: C[x][z] += kp^T @ [V|sinV] ----
        #pragma unroll
        for (int ks = 0; ks < 8; ks++) {
            int k0 = ks * 8;
            unsigned a[2][4];
            #pragma unroll
            for (int i = 0; i < 2; i++) {
                int xr = x0 + 16 * i + g;
                a[i][0] = sA[xr       * 76 + k0 + tig];
                a[i][1] = sA[(xr + 8) * 76 + k0 + tig];
                a[i][2] = sA[xr       * 76 + k0 + tig + 4];
                a[i][3] = sA[(xr + 8) * 76 + k0 + tig + 4];
            }
            #pragma unroll
            for (int nt = 0; nt < 4; nt++) {
                int z = z0 + 8 * nt + g;
                unsigned b0 = sV[(k0 + tig)     * 136 + z];
                unsigned b1 = sV[(k0 + tig + 4) * 136 + z];
                #pragma unroll
                for (int i = 0; i < 2; i++)
                    mma8(acc[i][nt], a[i][0], a[i][1], a[i][2], a[i][3], b0, b1);
            }
        }
        __syncthreads();

        // ---- restage next chunk ----
        if (cc + 1 < NCH) {
            int scs = sbase + (cc + 1) * CH;
            #pragma unroll
            for (int t = 0; t < 4; t++) {
                int idx = tid + t * 256; int r = idx >> 4, c4 = idx & 15;
                size_t gi = ((size_t)(b * Sn + scs + r)) * 16 + c4;
                float4 k = key4[gi], v = value4[gi];
                int kb = 4 * c4;
                *(uint4*)&sK[r * 68 + kb] = make_uint4(tf32c(k.x), tf32c(k.y), tf32c(k.z), tf32c(k.w));
                float sn = __sinf(PIC * (float)(scs + r) / (float)Sn);
                *(uint4*)&sV[r * 136 + kb]      = make_uint4(tf32c(v.x), tf32c(v.y), tf32c(v.z), tf32c(v.w));
                *(uint4*)&sV[r * 136 + 64 + kb] = make_uint4(tf32c(v.x*sn), tf32c(v.y*sn), tf32c(v.z*sn), tf32c(v.w*sn));
            }
            if (tid < 64) sSin[tid] = __sinf(PIC * (float)(scs + tid) / (float)Sn);
            __syncthreads();
        }
    }

    // ---- write fp32 C partials: [x 0..63][z 0..127] ----
    {
        size_t base = ((size_t)(split * 64 + bh)) * 8192;
        #pragma unroll
        for (int i = 0; i < 2; i++)
            #pragma unroll
            for (int nt = 0; nt < 4; nt++) {
                int x = x0 + 16 * i + g;
                int z = z0 + 8 * nt + 2 * tig;
                *(float2*)&g_part[base + (size_t)x       * 128 + z] = make_float2(acc[i][nt][0], acc[i][nt][1]);
                *(float2*)&g_part[base + (size_t)(x + 8) * 128 + z] = make_float2(acc[i][nt][2], acc[i][nt][3]);
            }
    }

    // ---- ksum reduce: shfl over g-lanes, stash per m-tile, combine ----
    #pragma unroll
    for (int off = 4; off <= 16; off <<= 1)
        #pragma unroll
        for (int nt = 0; nt < 4; nt++)
            #pragma unroll
            for (int e = 0; e < 2; e++) {
                kc [nt][e] += __shfl_xor_sync(0xffffffffu, kc [nt][e], off);
                kpc[nt][e] += __shfl_xor_sync(0xffffffffu, kpc[nt][e], off);
            }
    if (g == 0) {
        int mt = wid & 3;
        #pragma unroll
        for (int nt = 0; nt < 4; nt++)
            #pragma unroll
            for (int e = 0; e < 2; e++) {
                int x = n0p + 8 * nt + 2 * tig + e;
                sKred[mt * 128 + x]      = kc [nt][e];
                sKred[mt * 128 + 64 + x] = kpc[nt][e];
            }
    }
    __syncthreads();
    if (tid < 128)
        g_partKs[(split * 64 + bh) * 128 + tid] =
            sKred[tid] + sKred[128 + tid] + sKred[256 + tid] + sKred[384 + tid];
}

// ===========================================================================
// Kernel 2: per bh — reduce partials, fold V-proj + dense (fp32 SIMT):
//   G = Wv_h @ Wd_h ; bvd = bv_h @ Wd_h
//   M/Mp = Cstk @ G + Ksum (outer) bvd -> g_Mst, M/Mp INTERLEAVED pair layout
// ===========================================================================
constexpr int PAD = 68;
__global__ __launch_bounds__(256)
void mprep_kernel(const float* __restrict__ wv_w, const float* __restrict__ wv_b,
                  const float* __restrict__ dense_w)
{
    extern __shared__ float sm[];
    float* sC    = sm;                   // 128*68 (stacked rows [KV;KVp])
    float* sWv   = sC   + 128 * PAD;     // 64*68
    float* sWd   = sWv  + 64 * PAD;      // 64*68
    float* sG    = sWd  + 64 * PAD;      // 64*68
    float* sKsum = sG   + 64 * PAD;      // 128
    float* sBvd  = sKsum + 128;          // 64
    const float4* g_part4 = (const float4*)g_part;

    const int bh = blockIdx.x, h = bh & 15, tid = threadIdx.x;

    #pragma unroll
    for (int t = 0; t < 16; t++) {
        int i = tid + t * 256; int k = i >> 6, c = i & 63;
        sWv[k * PAD + c] = wv_w[k * 1024 + h * 64 + c];
        sWd[k * PAD + c] = dense_w[(h * 64 + k) * 64 + c];
    }
    // reduce partials; remap [x][z<64 | z>=64] -> stacked rows [x ; x+64]
    #pragma unroll
    for (int t = 0; t < 8; t++) {
        int idx = tid + t * 256;            // float4 index over 2048
        int x = idx >> 5, c8 = idx & 31;
        float4 s = make_float4(0.f, 0.f, 0.f, 0.f);
        for (int sl = 0; sl < NSPLIT; sl++) {
            float4 v = g_part4[((size_t)(sl * 64 + bh)) * 2048 + idx];
            s.x += v.x; s.y += v.y; s.z += v.z; s.w += v.w;
        }
        int row = (c8 < 16) ? x : (x + 64);
        int c4  = c8 & 15;
        *(float4*)&sC[row * PAD + c4 * 4] = s;
    }
    if (tid < 128) {
        float s = 0.f;
        for (int sl = 0; sl < NSPLIT; sl++) s += g_partKs[(sl * 64 + bh) * 128 + tid];
        sKsum[tid] = s;
        g_Ks[bh * 128 + tid] = s;
    }
    __syncthreads();

    const int r  = tid >> 2;
    const int c0 = (tid & 3) * 16;

    // G = Wv @ Wd
    {
        float a16[16];
        #pragma unroll
        for (int j = 0; j < 16; j++) a16[j] = 0.f;
        for (int kk = 0; kk < 64; kk++) {
            float a = sWv[r * PAD + kk];
            #pragma unroll
            for (int j = 0; j < 16; j++) a16[j] += a * sWd[kk * PAD + c0 + j];
        }
        #pragma unroll
        for (int j = 0; j < 16; j++) sG[r * PAD + c0 + j] = a16[j];
    }
    if (tid < 64) {
        float s = 0.f;
        for (int c = 0; c < 64; c++) s += wv_b[h * 64 + c] * sWd[c * PAD + tid];
        sBvd[tid] = s;
    }
    __syncthreads();

    // M/Mp = sC @ sG + ksum (outer) bvd -> g_Mst interleaved (free permute)
    {
        float m0[16], m1[16];
        #pragma unroll
        for (int j = 0; j < 16; j++) { m0[j] = 0.f; m1[j] = 0.f; }
        for (int kk = 0; kk < 64; kk++) {
            float a0 = sC[r * PAD + kk];
            float a1 = sC[(r + 64) * PAD + kk];
            #pragma unroll
            for (int j = 0; j < 16; j++) {
                float gv = sG[kk * PAD + c0 + j];
                m0[j] += a0 * gv; m1[j] += a1 * gv;
            }
        }
        float k0 = sKsum[r], k1 = sKsum[r + 64];
        #pragma unroll
        for (int j = 0; j < 16; j++) {
            m0[j] += k0 * sBvd[c0 + j];
            m1[j] += k1 * sBvd[c0 + j];
        }
        unsigned* dst = &g_Mst[(size_t)bh * 8192];
        #pragma unroll
        for (int j = 0; j < 16; j++) {
            int w0 = bpair2(r, c0 + j);   // even -> uint2-aligned
            *(uint2*)&dst[w0] = make_uint2(tf32c(m0[j]), tf32c(m1[j]));
        }
    }
}

// ===========================================================================
// Kernel 3 (tensor): per (b, 64-row s-tile), loop heads:
//   q = elu1(rawQ @ Wq_h + bq); den; o = q@M + w*(q@Mp)  [split GEMM, K=64,
//   both B fragments per (k,n) fetched with ONE LDS.128 from interleaved sB]
// ===========================================================================
__global__ __launch_bounds__(256, 2)
void out_kernel(const float4* __restrict__ query4,
                const float4* __restrict__ wq_w4, const float* __restrict__ wq_b,
                const float* __restrict__ dense_b, float* __restrict__ out)
{
    extern __shared__ unsigned smu[];
    unsigned* sQraw = smu;                  // 64 x 68  tf32 raw Q
    unsigned* sWq   = sQraw + 64 * 68;      // 64 x 72  tf32 Wq head slice
    unsigned* sB    = sWq   + 64 * 72;      // 8192     M/Mp interleaved pair layout
    unsigned* sQ    = sB    + 8192;         // 64 x 68  tf32 q (elu'd)
    float* sKs  = (float*)(sQ + 64 * 68);   // 128
    float* sWs  = sKs + 128;                // 64
    float* sQb  = sWs + 64;                 // 64
    float* sDot = sQb + 64;                 // 64 x 4

    const int b  = blockIdx.y;
    const int s0 = blockIdx.x * 64;
    const int tid = threadIdx.x;
    const int lane = tid & 31, wid = tid >> 5;
    const int g = lane >> 2, tig = lane & 3;
    const int mt = wid & 3, nh = wid >> 2;
    const int m0 = mt * 16, n0 = nh * 32;

    #pragma unroll
    for (int t = 0; t < 4; t++) {
        int idx = tid + t * 256; int r = idx >> 4, c4 = idx & 15;
        float4 q = query4[((size_t)(b * Sn + s0 + r)) * 16 + c4];
        *(uint4*)&sQraw[r * 68 + c4 * 4] = make_uint4(tf32c(q.x), tf32c(q.y), tf32c(q.z), tf32c(q.w));
    }
    if (tid < 64) {
        float ps = PIC * (float)(s0 + tid) / (float)Sn;
        sWs[tid] = __cosf(ps) + __sinf(ps);
    }

    float accO[4][4];
    #pragma unroll
    for (int nt = 0; nt < 4; nt++)
        #pragma unroll
        for (int j = 0; j < 4; j++) accO[nt][j] = 0.f;
    __syncthreads();

    const uint4* g_Mst4 = (const uint4*)g_Mst;

    for (int h = 0; h < Hn; h++) {
        const int bh = b * 16 + h;
        #pragma unroll
        for (int t = 0; t < 4; t++) {
            int idx = tid + t * 256; int d = idx >> 4, c4 = idx & 15;
            float4 w = wq_w4[d * 256 + h * 16 + c4];
            *(uint4*)&sWq[d * 72 + c4 * 4] = make_uint4(tf32c(w.x), tf32c(w.y), tf32c(w.z), tf32c(w.w));
        }
        #pragma unroll
        for (int t = 0; t < 8; t++) {
            int idx = tid + t * 256;
            *(uint4*)&sB[idx * 4] = g_Mst4[(size_t)bh * 2048 + idx];
        }
        if (tid < 128)      sKs[tid] = g_Ks[bh * 128 + tid];
        else if (tid < 192) sQb[tid - 128] = wq_b[h * 64 + (tid - 128)];
        __syncthreads();

        // ---- q projection mma ----
        float pc[4][4];
        #pragma unroll
        for (int nt = 0; nt < 4; nt++) {
            int col0 = n0 + 8 * nt + 2 * tig;
            pc[nt][0] = sQb[col0]; pc[nt][1] = sQb[col0 + 1];
            pc[nt][2] = sQb[col0]; pc[nt][3] = sQb[col0 + 1];
        }
        #pragma unroll
        for (int ks = 0; ks < 8; ks++) {
            int k0 = ks * 8;
            unsigned a0 = sQraw[(m0 + g)     * 68 + k0 + tig];
            unsigned a1 = sQraw[(m0 + g + 8) * 68 + k0 + tig];
            unsigned a2 = sQraw[(m0 + g)     * 68 + k0 + tig + 4];
            unsigned a3 = sQraw[(m0 + g + 8) * 68 + k0 + tig + 4];
            #pragma unroll
            for (int nt = 0; nt < 4; nt++) {
                int n = n0 + 8 * nt + g;
                unsigned b0 = sWq[(k0 + tig)     * 72 + n];
                unsigned b1 = sWq[(k0 + tig + 4) * 72 + n];
                mma8(pc[nt], a0, a1, a2, a3, b0, b1);
            }
        }

        // ---- elu, partial denominators, store q (K=64, no wq) ----
        {
            int r1 = (m0 + g) * 68, r2 = (m0 + g + 8) * 68;
            float d0a = 0.f, d1a = 0.f, d0b = 0.f, d1b = 0.f;
            #pragma unroll
            for (int nt = 0; nt < 4; nt++) {
                int col0 = n0 + 8 * nt + 2 * tig;
                float ks0 = sKs[col0],      ks1 = sKs[col0 + 1];
                float kp0 = sKs[64 + col0], kp1 = sKs[64 + col0 + 1];
                float v00 = elu1(pc[nt][0]), v01 = elu1(pc[nt][1]);
                float v10 = elu1(pc[nt][2]), v11 = elu1(pc[nt][3]);
                d0a += v00 * ks0 + v01 * ks1;  d1a += v00 * kp0 + v01 * kp1;
                d0b += v10 * ks0 + v11 * ks1;  d1b += v10 * kp0 + v11 * kp1;
                sQ[r1 + col0]     = tf32c(v00);
                sQ[r1 + col0 + 1] = tf32c(v01);
                sQ[r2 + col0]     = tf32c(v10);
                sQ[r2 + col0 + 1] = tf32c(v11);
            }
            d0a += __shfl_xor_sync(0xffffffffu, d0a, 1); d0a += __shfl_xor_sync(0xffffffffu, d0a, 2);
            d1a += __shfl_xor_sync(0xffffffffu, d1a, 1); d1a += __shfl_xor_sync(0xffffffffu, d1a, 2);
            d0b += __shfl_xor_sync(0xffffffffu, d0b, 1); d0b += __shfl_xor_sync(0xffffffffu, d0b, 2);
            d1b += __shfl_xor_sync(0xffffffffu, d1b, 1); d1b += __shfl_xor_sync(0xffffffffu, d1b, 2);
            if (tig == 0) {
                sDot[(m0 + g) * 4 + nh]         = d0a;
                sDot[(m0 + g) * 4 + 2 + nh]     = d1a;
                sDot[(m0 + g + 8) * 4 + nh]     = d0b;
                sDot[(m0 + g + 8) * 4 + 2 + nh] = d1b;
            }
        }
        __syncthreads();

        int r1 = m0 + g, r2 = m0 + g + 8;
        float w1 = sWs[r1], w2 = sWs[r2];
        float den1 = 1.0f / (sDot[r1 * 4] + sDot[r1 * 4 + 1]
                     + w1 * (sDot[r1 * 4 + 2] + sDot[r1 * 4 + 3]) + 1e-5f);
        float den2 = 1.0f / (sDot[r2 * 4] + sDot[r2 * 4 + 1]
                     + w2 * (sDot[r2 * 4 + 2] + sDot[r2 * 4 + 3]) + 1e-5f);
        float dnw1 = den1 * w1, dnw2 = den2 * w2;

        // ---- split o-GEMM: ocM = q@M, ocP = q@Mp (K=64, shared A, fused B LDS.128) ----
        float ocM[4][4], ocP[4][4];
        #pragma unroll
        for (int nt = 0; nt < 4; nt++)
            #pragma unroll
            for (int j = 0; j < 4; j++) { ocM[nt][j] = 0.f; ocP[nt][j] = 0.f; }
        #pragma unroll
        for (int ks = 0; ks < 8; ks++) {
            int k0 = ks * 8;
            unsigned a0 = sQ[(m0 + g)     * 68 + k0 + tig];
            unsigned a1 = sQ[(m0 + g + 8) * 68 + k0 + tig];
            unsigned a2 = sQ[(m0 + g)     * 68 + k0 + tig + 4];
            unsigned a3 = sQ[(m0 + g + 8) * 68 + k0 + tig + 4];
            #pragma unroll
            for (int nt = 0; nt < 4; nt++) {
                int n = n0 + 8 * nt + g;
                uint4 bb = *(const uint4*)&sB[(ks * 64 + n) * 16 + tig * 4];
                mma8(ocM[nt], a0, a1, a2, a3, bb.x, bb.z);
                mma8(ocP[nt], a0, a1, a2, a3, bb.y, bb.w);
            }
        }
        #pragma unroll
        for (int nt = 0; nt < 4; nt++) {
            accO[nt][0] += den1 * ocM[nt][0] + dnw1 * ocP[nt][0];
            accO[nt][1] += den1 * ocM[nt][1] + dnw1 * ocP[nt][1];
            accO[nt][2] += den2 * ocM[nt][2] + dnw2 * ocP[nt][2];
            accO[nt][3] += den2 * ocM[nt][3] + dnw2 * ocP[nt][3];
        }
        __syncthreads();
    }

    // ---- epilogue: + dense_b ----
    #pragma unroll
    for (int nt = 0; nt < 4; nt++) {
        int col0 = n0 + 8 * nt + 2 * tig;
        float db0 = dense_b[col0], db1 = dense_b[col0 + 1];
        size_t o1 = ((size_t)(b * Sn + s0 + m0 + g)) * 64 + col0;
        size_t o2 = ((size_t)(b * Sn + s0 + m0 + g + 8)) * 64 + col0;
        out[o1]     = accO[nt][0] + db0;
        out[o1 + 1] = accO[nt][1] + db1;
        out[o2]     = accO[nt][2] + db0;
        out[o2 + 1] = accO[nt][3] + db1;
    }
}

// ---------------------------------------------------------------------------
extern "C" void kernel_launch(void* const* d_in, const int* in_sizes, int n_in,
                              void* d_out, int out_size)
{
    const float4* query4  = (const float4*)d_in[0];
    const float4* key4    = (const float4*)d_in[1];
    const float4* value4  = (const float4*)d_in[2];
    // d_in[3] = attn_mask (unused by the math)
    const float4* wq_w4   = (const float4*)d_in[4];
    const float*  wq_b    = (const float*)d_in[5];
    const float4* wk_w4   = (const float4*)d_in[6];
    const float*  wk_b    = (const float*)d_in[7];
    const float*  wv_w    = (const float*)d_in[8];
    const float*  wv_b    = (const float*)d_in[9];
    const float*  dense_w = (const float*)d_in[10];
    const float*  dense_b = (const float*)d_in[11];
    float* out = (float*)d_out;

    constexpr int SM_KV  = (4096 + 64*68 + 64*136 + 64*76 + 64 + 64 + 512) * 4;   // 90,624 B
    constexpr int SM_MP  = (128 * PAD + 3 * 64 * PAD + 128 + 64) * 4;             // 87,808 B
    constexpr int SM_OUT = (64*68 + 64*72 + 8192 + 64*68 + 128+64+64+256) * 4;    // 88,064 B

    cudaFuncSetAttribute(kv_kernel,    cudaFuncAttributeMaxDynamicSharedMemorySize, SM_KV);
    cudaFuncSetAttribute(mprep_kernel, cudaFuncAttributeMaxDynamicSharedMemorySize, SM_MP);
    cudaFuncSetAttribute(out_kernel,   cudaFuncAttributeMaxDynamicSharedMemorySize, SM_OUT);

    kv_kernel   <<<dim3(BHn, NSPLIT), 256, SM_KV >>>(key4, value4, wk_w4, wk_b);
    mprep_kernel<<<BHn,               256, SM_MP >>>(wv_w, wv_b, dense_w);
    out_kernel  <<<dim3(Sn / 64, Bn), 256, SM_OUT>>>(query4, wq_w4, wq_b, dense_b, out);
}